// round 2
// baseline (speedup 1.0000x reference)
#include <cuda_runtime.h>

#define FAN 10
constexpr int IN_DIM = 128;
constexpr int HID    = 256;
constexpr int Bsz    = 4096;
constexpr int N2n    = 3 * Bsz;       // 12288
constexpr int N1n    = N2n * FAN;     // 122880
constexpr int ZROWS  = 2 * Bsz;       // 8192

// ---- scratch (device globals: allocation-free) ----
__device__ __align__(16) float g_u0[(size_t)N1n * HID];        // [N1, 256]  self|agg layer0 input
__device__ __align__(16) float g_h0[(size_t)N1n * HID];        // [N1, 256]  layer0 output
__device__ __align__(16) float g_u1[(size_t)N2n * 2 * HID];    // [N2, 512]  self|agg layer1 input
__device__ __align__(16) float g_h2[(size_t)N2n * HID];        // [N2, 256]  layer1 output
__device__ __align__(16) float g_z0[(size_t)ZROWS * HID];      // [8192,256]
__device__ __align__(16) float g_z1[(size_t)ZROWS * HID];      // [8192,256]
__device__ __align__(16) float g_Wc0[HID * HID];               // [256,256] = [Ws0; Wn0]
__device__ __align__(16) float g_Wc1[2 * HID * HID];           // [512,256] = [Ws1; Wn1]

// ---- packed fp32x2 helpers (sm_103a: fma.rn.f32x2 doubles FFMA throughput) ----
__device__ __forceinline__ unsigned long long dup_f32x2(float x) {
    unsigned long long r;
    asm("mov.b64 %0, {%1, %1};" : "=l"(r) : "f"(x));
    return r;
}
__device__ __forceinline__ float2 unpack_f32x2(unsigned long long v) {
    float2 r;
    asm("mov.b64 {%0, %1}, %2;" : "=f"(r.x), "=f"(r.y) : "l"(v));
    return r;
}
#define FFMA2(d, a, b) asm("fma.rn.f32x2 %0, %1, %2, %0;" : "+l"(d) : "l"(a), "l"(b))

// ---- weight packing: Wc0 = [Ws0; Wn0], Wc1 = [Ws1; Wn1] ----
__global__ void pack_weights(const float* __restrict__ Ws0, const float* __restrict__ Wn0,
                             const float* __restrict__ Ws1, const float* __restrict__ Wn1) {
    int r = blockIdx.x, c = threadIdx.x;   // grid 512, block 256
    if (r < HID)
        g_Wc0[r * HID + c] = (r < IN_DIM) ? Ws0[r * HID + c] : Wn0[(r - IN_DIM) * HID + c];
    g_Wc1[r * HID + c] = (r < HID) ? Ws1[r * HID + c] : Wn1[(r - HID) * HID + c];
}

// ---- layer0 gather + mean: u0[i] = [ nf[gids[i]] | mean_k nf[gids[nidx[i,k]]] ] ----
__global__ void gather_agg0(const float* __restrict__ nf, const int* __restrict__ gids,
                            const int* __restrict__ nidx) {
    int gw   = (blockIdx.x * blockDim.x + threadIdx.x) >> 5;  // dst row, exact grid
    int lane = threadIdx.x & 31;

    int idx_l = 0;
    if (lane < FAN)       idx_l = gids[nidx[(size_t)gw * FAN + lane]];
    else if (lane == FAN) idx_l = gids[gw];

    float4 v[FAN];
    #pragma unroll
    for (int k = 0; k < FAN; k++) {
        int g = __shfl_sync(0xffffffffu, idx_l, k);
        v[k] = __ldg((const float4*)nf + (size_t)g * (IN_DIM / 4) + lane);
    }
    int gs = __shfl_sync(0xffffffffu, idx_l, FAN);
    float4 s = __ldg((const float4*)nf + (size_t)gs * (IN_DIM / 4) + lane);

    float4 a = make_float4(0.f, 0.f, 0.f, 0.f);
    #pragma unroll
    for (int k = 0; k < FAN; k++) { a.x += v[k].x; a.y += v[k].y; a.z += v[k].z; a.w += v[k].w; }
    const float inv = 1.0f / FAN;
    a.x *= inv; a.y *= inv; a.z *= inv; a.w *= inv;

    float4* u = (float4*)(g_u0 + (size_t)gw * HID);
    u[lane]      = s;   // cols 0..127   (self)
    u[32 + lane] = a;   // cols 128..255 (agg)
}

// ---- layer1 gather + mean over g_h0: u1[i] = [ h0[i] | mean_k h0[nidx1[i,k]] ] ----
__global__ void gather_agg1(const int* __restrict__ nidx) {
    int gw   = (blockIdx.x * blockDim.x + threadIdx.x) >> 5;
    int lane = threadIdx.x & 31;

    int idx_l = (lane < FAN) ? nidx[(size_t)gw * FAN + lane] : 0;

    float4 a0 = make_float4(0.f, 0.f, 0.f, 0.f), a1 = a0;
    #pragma unroll
    for (int k = 0; k < FAN; k++) {
        int j = __shfl_sync(0xffffffffu, idx_l, k);
        const float4* row = (const float4*)g_h0 + (size_t)j * (HID / 4);
        float4 v0 = __ldg(row + lane);
        float4 v1 = __ldg(row + 32 + lane);
        a0.x += v0.x; a0.y += v0.y; a0.z += v0.z; a0.w += v0.w;
        a1.x += v1.x; a1.y += v1.y; a1.z += v1.z; a1.w += v1.w;
    }
    const float4* srow = (const float4*)g_h0 + (size_t)gw * (HID / 4);
    float4 s0 = __ldg(srow + lane), s1 = __ldg(srow + 32 + lane);

    const float inv = 1.0f / FAN;
    a0.x *= inv; a0.y *= inv; a0.z *= inv; a0.w *= inv;
    a1.x *= inv; a1.y *= inv; a1.z *= inv; a1.w *= inv;

    float4* u = (float4*)(g_u1 + (size_t)gw * (2 * HID));
    u[lane] = s0; u[32 + lane] = s1;            // cols 0..255   (self)
    u[64 + lane] = a0; u[96 + lane] = a1;       // cols 256..511 (agg)
}

// ---- SIMT SGEMM with packed fp32x2 FFMA. C = act(A[M,K] @ B[K,N] + bias) ----
// BM=128, BN=128, BK=8; 256 threads; 8x8 per thread; double-buffered smem.
// Requires M%128==0, N%128==0, K%8==0 (all shapes here satisfy this).
template <bool RELU>
__global__ __launch_bounds__(256, 2) void sgemm_f32x2(
    const float* __restrict__ A, const float* __restrict__ Bw,
    const float* __restrict__ bias, float* __restrict__ C,
    int M, int N, int K)
{
    constexpr int BM = 128, BN = 128, BK = 8;
    __shared__ __align__(16) float As[2][BK][BM];
    __shared__ __align__(16) float Bs[2][BK][BN];

    const int tid = threadIdx.x;
    const int bm  = blockIdx.y * BM;
    const int bn  = blockIdx.x * BN;

    const int arow = tid >> 1;           // 0..127
    const int acol = (tid & 1) * 4;      // 0 or 4
    const int brow = tid >> 5;           // 0..7
    const int bcol = (tid & 31) * 4;     // 0..124

    const float* Ag = A  + (size_t)(bm + arow) * K + acol;
    const float* Bg = Bw + (size_t)brow * N + bn + bcol;

    float4 av = *(const float4*)Ag;
    float4 bv = *(const float4*)Bg;
    As[0][acol + 0][arow] = av.x; As[0][acol + 1][arow] = av.y;
    As[0][acol + 2][arow] = av.z; As[0][acol + 3][arow] = av.w;
    *(float4*)&Bs[0][brow][bcol] = bv;
    __syncthreads();

    const int tx = (tid & 15) * 8;       // n-offset of 8-wide micro tile
    const int ty = (tid >> 4) * 8;       // m-offset

    unsigned long long acc[8][4];
    #pragma unroll
    for (int i = 0; i < 8; i++)
        #pragma unroll
        for (int j = 0; j < 4; j++) acc[i][j] = 0ull;

    const int nT = K / BK;
    for (int t = 0; t < nT; t++) {
        const int cur = t & 1;
        if (t + 1 < nT) {
            av = *(const float4*)(Ag + (t + 1) * BK);
            bv = *(const float4*)(Bg + (size_t)(t + 1) * BK * N);
        }
        #pragma unroll
        for (int k = 0; k < BK; k++) {
            float4 af0 = *(const float4*)&As[cur][k][ty];
            float4 af1 = *(const float4*)&As[cur][k][ty + 4];
            ulonglong2 b01 = *(const ulonglong2*)&Bs[cur][k][tx];
            ulonglong2 b23 = *(const ulonglong2*)&Bs[cur][k][tx + 4];
            unsigned long long ad[8];
            ad[0] = dup_f32x2(af0.x); ad[1] = dup_f32x2(af0.y);
            ad[2] = dup_f32x2(af0.z); ad[3] = dup_f32x2(af0.w);
            ad[4] = dup_f32x2(af1.x); ad[5] = dup_f32x2(af1.y);
            ad[6] = dup_f32x2(af1.z); ad[7] = dup_f32x2(af1.w);
            #pragma unroll
            for (int i = 0; i < 8; i++) {
                FFMA2(acc[i][0], ad[i], b01.x);
                FFMA2(acc[i][1], ad[i], b01.y);
                FFMA2(acc[i][2], ad[i], b23.x);
                FFMA2(acc[i][3], ad[i], b23.y);
            }
        }
        if (t + 1 < nT) {
            const int nxt = 1 - cur;
            As[nxt][acol + 0][arow] = av.x; As[nxt][acol + 1][arow] = av.y;
            As[nxt][acol + 2][arow] = av.z; As[nxt][acol + 3][arow] = av.w;
            *(float4*)&Bs[nxt][brow][bcol] = bv;
            __syncthreads();
        }
    }

    float bb[8];
    #pragma unroll
    for (int j = 0; j < 8; j++) bb[j] = bias[bn + tx + j];

    #pragma unroll
    for (int i = 0; i < 8; i++) {
        float o[8]; float2 p;
        p = unpack_f32x2(acc[i][0]); o[0] = p.x + bb[0]; o[1] = p.y + bb[1];
        p = unpack_f32x2(acc[i][1]); o[2] = p.x + bb[2]; o[3] = p.y + bb[3];
        p = unpack_f32x2(acc[i][2]); o[4] = p.x + bb[4]; o[5] = p.y + bb[5];
        p = unpack_f32x2(acc[i][3]); o[6] = p.x + bb[6]; o[7] = p.y + bb[7];
        if (RELU) {
            #pragma unroll
            for (int j = 0; j < 8; j++) o[j] = fmaxf(o[j], 0.f);
        }
        float* cp = C + (size_t)(bm + ty + i) * N + bn + tx;
        *(float4*)cp       = make_float4(o[0], o[1], o[2], o[3]);
        *(float4*)(cp + 4) = make_float4(o[4], o[5], o[6], o[7]);
    }
}

// ---- z[r] = h2[r mod B] * h2[B + r]  (pos half then neg half) ----
__global__ void build_z() {
    int r = blockIdx.x, c = threadIdx.x;   // grid 8192, block 64, float4 each
    const float4* s = (const float4*)(g_h2 + (size_t)(r & (Bsz - 1)) * HID);
    const float4* o = (const float4*)(g_h2 + (size_t)(Bsz + r) * HID);
    float4 a = s[c], b = o[c];
    ((float4*)(g_z0 + (size_t)r * HID))[c] =
        make_float4(a.x * b.x, a.y * b.y, a.z * b.z, a.w * b.w);
}

// ---- scores = z2 @ Wp3 + bp3 : one warp per row (256-dot) ----
__global__ void final_dot(const float* __restrict__ Wp3, const float* __restrict__ bp3,
                          float* __restrict__ out) {
    int gw   = (blockIdx.x * blockDim.x + threadIdx.x) >> 5;
    int lane = threadIdx.x & 31;
    const float4* z = (const float4*)(g_z0 + (size_t)gw * HID);
    const float4* w = (const float4*)Wp3;
    float4 z0 = z[lane], z1 = z[32 + lane];
    float4 w0 = __ldg(w + lane), w1 = __ldg(w + 32 + lane);
    float s = z0.x * w0.x + z0.y * w0.y + z0.z * w0.z + z0.w * w0.w
            + z1.x * w1.x + z1.y * w1.y + z1.z * w1.z + z1.w * w1.w;
    #pragma unroll
    for (int o = 16; o; o >>= 1) s += __shfl_xor_sync(0xffffffffu, s, o);
    if (lane == 0) out[gw] = s + bp3[0];
}

extern "C" void kernel_launch(void* const* d_in, const int* in_sizes, int n_in,
                              void* d_out, int out_size) {
    const float* node_feat = (const float*)d_in[0];
    const int*   gids0     = (const int*)d_in[1];
    const int*   nidx0     = (const int*)d_in[2];
    const int*   nidx1     = (const int*)d_in[3];
    const float* Ws0 = (const float*)d_in[4];
    const float* Wn0 = (const float*)d_in[5];
    const float* b0  = (const float*)d_in[6];
    const float* Ws1 = (const float*)d_in[7];
    const float* Wn1 = (const float*)d_in[8];
    const float* b1  = (const float*)d_in[9];
    const float* Wp1 = (const float*)d_in[10];
    const float* bp1 = (const float*)d_in[11];
    const float* Wp2 = (const float*)d_in[12];
    const float* bp2 = (const float*)d_in[13];
    const float* Wp3 = (const float*)d_in[14];
    const float* bp3 = (const float*)d_in[15];
    float* out = (float*)d_out;

    float *u0, *h0, *u1, *h2, *z0, *z1, *Wc0, *Wc1;
    cudaGetSymbolAddress((void**)&u0,  g_u0);
    cudaGetSymbolAddress((void**)&h0,  g_h0);
    cudaGetSymbolAddress((void**)&u1,  g_u1);
    cudaGetSymbolAddress((void**)&h2,  g_h2);
    cudaGetSymbolAddress((void**)&z0,  g_z0);
    cudaGetSymbolAddress((void**)&z1,  g_z1);
    cudaGetSymbolAddress((void**)&Wc0, g_Wc0);
    cudaGetSymbolAddress((void**)&Wc1, g_Wc1);

    // weight packing (tiny)
    pack_weights<<<2 * HID, HID>>>(Ws0, Wn0, Ws1, Wn1);

    // layer 0: gather+mean, then fused GEMM+bias+relu
    gather_agg0<<<N1n / 8, 256>>>(node_feat, gids0, nidx0);
    sgemm_f32x2<true><<<dim3(HID / 128, N1n / 128), 256>>>(u0, Wc0, b0, h0, N1n, HID, 2 * IN_DIM);

    // layer 1: gather+mean over h0, then GEMM+bias (no relu)
    gather_agg1<<<N2n / 8, 256>>>(nidx1);
    sgemm_f32x2<false><<<dim3(HID / 128, N2n / 128), 256>>>(u1, Wc1, b1, h2, N2n, HID, 2 * HID);

    // edge MLP
    build_z<<<ZROWS, 64>>>();
    sgemm_f32x2<true><<<dim3(HID / 128, ZROWS / 128), 256>>>(z0, Wp1, bp1, z1, ZROWS, HID, HID);
    sgemm_f32x2<true><<<dim3(HID / 128, ZROWS / 128), 256>>>(z1, Wp2, bp2, z0, ZROWS, HID, HID);
    final_dot<<<ZROWS / 8, 256>>>(Wp3, bp3, out);
}

// round 4
// speedup vs baseline: 1.8633x; 1.8633x over previous
#include <cuda_runtime.h>
#include <cuda_bf16.h>
#include <cstdint>

#define FAN 10
constexpr int IN_DIM = 128;
constexpr int HID    = 256;
constexpr int Bsz    = 4096;
constexpr int N2n    = 3 * Bsz;       // 12288
constexpr int N1n    = N2n * FAN;     // 122880
constexpr int ZROWS  = 2 * Bsz;       // 8192

// ---------------- scratch (device globals: allocation-free) ----------------
__device__ __align__(16) __nv_bfloat16 g_u0h[(size_t)N1n * HID];
__device__ __align__(16) __nv_bfloat16 g_u0l[(size_t)N1n * HID];
__device__ __align__(16) float         g_h0 [(size_t)N1n * HID];
__device__ __align__(16) __nv_bfloat16 g_u1h[(size_t)N2n * 2 * HID];
__device__ __align__(16) __nv_bfloat16 g_u1l[(size_t)N2n * 2 * HID];
__device__ __align__(16) float         g_h2 [(size_t)N2n * HID];
__device__ __align__(16) __nv_bfloat16 g_zh [(size_t)ZROWS * HID];
__device__ __align__(16) __nv_bfloat16 g_zl [(size_t)ZROWS * HID];
__device__ __align__(16) __nv_bfloat16 g_z1h[(size_t)ZROWS * HID];
__device__ __align__(16) __nv_bfloat16 g_z1l[(size_t)ZROWS * HID];
__device__ __align__(16) float         g_z2 [(size_t)ZROWS * HID];
// transposed bf16 hi/lo weights: [N=256, K]
__device__ __align__(16) __nv_bfloat16 g_W0h[HID * HID],     g_W0l[HID * HID];
__device__ __align__(16) __nv_bfloat16 g_W1h[HID * 2 * HID], g_W1l[HID * 2 * HID];
__device__ __align__(16) __nv_bfloat16 g_P1h[HID * HID],     g_P1l[HID * HID];
__device__ __align__(16) __nv_bfloat16 g_P2h[HID * HID],     g_P2l[HID * HID];

// ---------------- PTX helpers (base sm_103-safe: mma.sync / ldmatrix / cp.async) ----
__device__ __forceinline__ uint32_t smem_u32(const void* p) {
    uint32_t a;
    asm("{ .reg .u64 t; cvta.to.shared.u64 t, %1; cvt.u32.u64 %0, t; }" : "=r"(a) : "l"(p));
    return a;
}
__device__ __forceinline__ void mma16816(float* d, const uint32_t* a, const uint32_t* b) {
    asm volatile("mma.sync.aligned.m16n8k16.row.col.f32.bf16.bf16.f32 "
                 "{%0,%1,%2,%3}, {%4,%5,%6,%7}, {%8,%9}, {%0,%1,%2,%3};"
                 : "+f"(d[0]), "+f"(d[1]), "+f"(d[2]), "+f"(d[3])
                 : "r"(a[0]), "r"(a[1]), "r"(a[2]), "r"(a[3]), "r"(b[0]), "r"(b[1]));
}
__device__ __forceinline__ void ldsm4(uint32_t* r, uint32_t addr) {
    asm volatile("ldmatrix.sync.aligned.m8n8.x4.shared.b16 {%0,%1,%2,%3}, [%4];"
                 : "=r"(r[0]), "=r"(r[1]), "=r"(r[2]), "=r"(r[3]) : "r"(addr));
}
#define CP16(dst, src) asm volatile("cp.async.cg.shared.global [%0], [%1], 16;" :: "r"(dst), "l"(src))
#define CP_COMMIT()    asm volatile("cp.async.commit_group;" ::: "memory")
#define CP_WAIT1()     asm volatile("cp.async.wait_group 1;" ::: "memory")
#define CP_WAIT0()     asm volatile("cp.async.wait_group 0;" ::: "memory")

// ---------------- bf16 hi/lo split helpers ----------------
__device__ __forceinline__ __nv_bfloat16 bf_hi(float v) { return __float2bfloat16_rn(v); }
__device__ __forceinline__ void split_store4(__nv_bfloat16* ph, __nv_bfloat16* pl, float4 v) {
    __nv_bfloat16 hx = bf_hi(v.x), hy = bf_hi(v.y), hz = bf_hi(v.z), hw = bf_hi(v.w);
    __nv_bfloat162 h01, h23, l01, l23;
    h01.x = hx; h01.y = hy; h23.x = hz; h23.y = hw;
    l01.x = bf_hi(v.x - __bfloat162float(hx)); l01.y = bf_hi(v.y - __bfloat162float(hy));
    l23.x = bf_hi(v.z - __bfloat162float(hz)); l23.y = bf_hi(v.w - __bfloat162float(hw));
    uint2 H, L;
    H.x = *(unsigned*)&h01; H.y = *(unsigned*)&h23;
    L.x = *(unsigned*)&l01; L.y = *(unsigned*)&l23;
    *(uint2*)ph = H; *(uint2*)pl = L;
}
__device__ __forceinline__ void split_store2(__nv_bfloat16* ph, __nv_bfloat16* pl, float2 v) {
    __nv_bfloat16 hx = bf_hi(v.x), hy = bf_hi(v.y);
    __nv_bfloat162 h, l;
    h.x = hx; h.y = hy;
    l.x = bf_hi(v.x - __bfloat162float(hx)); l.y = bf_hi(v.y - __bfloat162float(hy));
    *(unsigned*)ph = *(unsigned*)&h;
    *(unsigned*)pl = *(unsigned*)&l;
}

// ---------------- weight packing (transposed bf16 hi/lo) ----------------
__global__ void pack_weights(const float* __restrict__ Ws0, const float* __restrict__ Wn0,
                             const float* __restrict__ Ws1, const float* __restrict__ Wn1,
                             const float* __restrict__ Wp1, const float* __restrict__ Wp2) {
    int n = blockIdx.x, k = threadIdx.x;   // 256 x 256
    auto split1 = [](float v, __nv_bfloat16* h, __nv_bfloat16* l) {
        __nv_bfloat16 hb = __float2bfloat16_rn(v);
        *h = hb; *l = __float2bfloat16_rn(v - __bfloat162float(hb));
    };
    float w0 = (k < IN_DIM) ? Ws0[k * HID + n] : Wn0[(k - IN_DIM) * HID + n];
    split1(w0, &g_W0h[n * HID + k], &g_W0l[n * HID + k]);
    split1(Wp1[k * HID + n], &g_P1h[n * HID + k], &g_P1l[n * HID + k]);
    split1(Wp2[k * HID + n], &g_P2h[n * HID + k], &g_P2l[n * HID + k]);
    split1(Ws1[k * HID + n], &g_W1h[n * 2 * HID + k],       &g_W1l[n * 2 * HID + k]);
    split1(Wn1[k * HID + n], &g_W1h[n * 2 * HID + k + HID], &g_W1l[n * 2 * HID + k + HID]);
}

// ---------------- layer0 gather + mean -> bf16 hi/lo ----------------
__global__ void gather_agg0(const float* __restrict__ nf, const int* __restrict__ gids,
                            const int* __restrict__ nidx) {
    int gw   = (blockIdx.x * blockDim.x + threadIdx.x) >> 5;
    int lane = threadIdx.x & 31;

    int idx_l = 0;
    if (lane < FAN)       idx_l = gids[nidx[(size_t)gw * FAN + lane]];
    else if (lane == FAN) idx_l = gids[gw];

    float4 v[FAN];
    #pragma unroll
    for (int k = 0; k < FAN; k++) {
        int g = __shfl_sync(0xffffffffu, idx_l, k);
        v[k] = __ldg((const float4*)nf + (size_t)g * (IN_DIM / 4) + lane);
    }
    int gs = __shfl_sync(0xffffffffu, idx_l, FAN);
    float4 s = __ldg((const float4*)nf + (size_t)gs * (IN_DIM / 4) + lane);

    float4 a = make_float4(0.f, 0.f, 0.f, 0.f);
    #pragma unroll
    for (int k = 0; k < FAN; k++) { a.x += v[k].x; a.y += v[k].y; a.z += v[k].z; a.w += v[k].w; }
    const float inv = 1.0f / FAN;
    a.x *= inv; a.y *= inv; a.z *= inv; a.w *= inv;

    size_t rb = (size_t)gw * HID;
    split_store4(g_u0h + rb + 4 * lane,       g_u0l + rb + 4 * lane,       s);
    split_store4(g_u0h + rb + 128 + 4 * lane, g_u0l + rb + 128 + 4 * lane, a);
}

// ---------------- layer1 gather + mean over g_h0 -> bf16 hi/lo ----------------
__global__ void gather_agg1(const int* __restrict__ nidx) {
    int gw   = (blockIdx.x * blockDim.x + threadIdx.x) >> 5;
    int lane = threadIdx.x & 31;

    int idx_l = (lane < FAN) ? nidx[(size_t)gw * FAN + lane] : 0;

    float4 a0 = make_float4(0.f, 0.f, 0.f, 0.f), a1 = a0;
    #pragma unroll
    for (int k = 0; k < FAN; k++) {
        int j = __shfl_sync(0xffffffffu, idx_l, k);
        const float4* row = (const float4*)g_h0 + (size_t)j * (HID / 4);
        float4 v0 = __ldg(row + lane);
        float4 v1 = __ldg(row + 32 + lane);
        a0.x += v0.x; a0.y += v0.y; a0.z += v0.z; a0.w += v0.w;
        a1.x += v1.x; a1.y += v1.y; a1.z += v1.z; a1.w += v1.w;
    }
    const float4* srow = (const float4*)g_h0 + (size_t)gw * (HID / 4);
    float4 s0 = __ldg(srow + lane), s1 = __ldg(srow + 32 + lane);

    const float inv = 1.0f / FAN;
    a0.x *= inv; a0.y *= inv; a0.z *= inv; a0.w *= inv;
    a1.x *= inv; a1.y *= inv; a1.z *= inv; a1.w *= inv;

    size_t rb = (size_t)gw * (2 * HID);
    split_store4(g_u1h + rb + 4 * lane,       g_u1l + rb + 4 * lane,       s0);
    split_store4(g_u1h + rb + 128 + 4 * lane, g_u1l + rb + 128 + 4 * lane, s1);
    split_store4(g_u1h + rb + 256 + 4 * lane, g_u1l + rb + 256 + 4 * lane, a0);
    split_store4(g_u1h + rb + 384 + 4 * lane, g_u1l + rb + 384 + 4 * lane, a1);
}

// ---------------- HMMA GEMM: C[M,256] = act(A[M,K] @ W[K,256] + bias) ----------------
// A as bf16 hi/lo [M,K] row-major; W as transposed bf16 hi/lo Bt[256,K].
// 3-pass split: D += Ah*Bh + Ah*Bl + Al*Bh (fp32 accum via mma.sync.m16n8k16).
// BM=128, BN=128, BK=32; 256 threads = 8 warps (2m x 4n), warp tile 64x32.
// smem: 2 stages x (Ah 8K | Al 8K | Bh 8K | Bl 8K) = 64 KB dynamic.
constexpr int GEMM_SMEM = 65536;

template <bool RELU, bool SPLIT>
__global__ void __launch_bounds__(256, 1) hgemm(
    const __nv_bfloat16* __restrict__ Ah, const __nv_bfloat16* __restrict__ Al,
    const __nv_bfloat16* __restrict__ Bh, const __nv_bfloat16* __restrict__ Bl,
    const float* __restrict__ bias,
    float* __restrict__ Cf, __nv_bfloat16* __restrict__ Ch, __nv_bfloat16* __restrict__ Cl,
    int K)
{
    extern __shared__ char sm[];
    const uint32_t sb = smem_u32(sm);
    const int tid = threadIdx.x, lane = tid & 31, wid = tid >> 5;
    const int bm = blockIdx.y * 128, bn = blockIdx.x * 128;
    const int wm = (wid >> 2) * 64, wn = (wid & 3) * 32;
    const int nCh = K >> 5;                 // BK=32 chunks

    // smem tile offset: [128 rows][4 x 16B chunks], xor-swizzled chunk
    auto swo = [](int r, int c) -> uint32_t { return (uint32_t)(r * 64 + ((c ^ ((r >> 1) & 3)) << 4)); };

    auto load_stage = [&](int stage, int kc) {
        const uint32_t base = sb + stage * 32768;
        #pragma unroll
        for (int i = 0; i < 2; i++) {
            int q = tid + i * 256;          // 512 chunks per tile
            int r = q >> 2, c = q & 3;
            uint32_t so = swo(r, c);
            size_t ga = (size_t)(bm + r) * K + kc * 32 + c * 8;
            size_t gb = (size_t)(bn + r) * K + kc * 32 + c * 8;
            CP16(base +         so, Ah + ga);
            CP16(base +  8192 + so, Al + ga);
            CP16(base + 16384 + so, Bh + gb);
            CP16(base + 24576 + so, Bl + gb);
        }
    };

    float acc[4][4][4];
    #pragma unroll
    for (int i = 0; i < 4; i++)
        #pragma unroll
        for (int j = 0; j < 4; j++)
            #pragma unroll
            for (int k = 0; k < 4; k++) acc[i][j][k] = 0.f;

    load_stage(0, 0);
    CP_COMMIT();

    for (int kc = 0; kc < nCh; kc++) {
        if (kc + 1 < nCh) { load_stage((kc + 1) & 1, kc + 1); CP_COMMIT(); CP_WAIT1(); }
        else              { CP_WAIT0(); }
        __syncthreads();

        const uint32_t base = sb + (kc & 1) * 32768;
        #pragma unroll
        for (int ks = 0; ks < 2; ks++) {
            uint32_t aH[4][4], aL[4][4], bH[2][4], bL[2][4];
            #pragma unroll
            for (int mt = 0; mt < 4; mt++) {
                int row = wm + mt * 16 + (lane & 15);
                int kch = 2 * ks + (lane >> 4);
                uint32_t so = swo(row, kch);
                ldsm4(aH[mt], base + so);
                ldsm4(aL[mt], base + 8192 + so);
            }
            #pragma unroll
            for (int p = 0; p < 2; p++) {
                int row = wn + p * 16 + (lane & 7) + ((lane >> 4) << 3);
                int kch = 2 * ks + ((lane >> 3) & 1);
                uint32_t so = swo(row, kch);
                ldsm4(bH[p], base + 16384 + so);
                ldsm4(bL[p], base + 24576 + so);
            }
            #pragma unroll
            for (int mt = 0; mt < 4; mt++) {
                #pragma unroll
                for (int nt = 0; nt < 4; nt++) {
                    const uint32_t* bh = &bH[nt >> 1][(nt & 1) * 2];
                    const uint32_t* bl = &bL[nt >> 1][(nt & 1) * 2];
                    mma16816(acc[mt][nt], aH[mt], bh);
                    mma16816(acc[mt][nt], aH[mt], bl);
                    mma16816(acc[mt][nt], aL[mt], bh);
                }
            }
        }
        __syncthreads();
    }

    // epilogue: direct float2 stores (+bias, act)
    const int tg = lane >> 2, tt = lane & 3;
    #pragma unroll
    for (int nt = 0; nt < 4; nt++) {
        int col = bn + wn + nt * 8 + 2 * tt;
        float2 b2 = *(const float2*)(bias + col);
        #pragma unroll
        for (int mt = 0; mt < 4; mt++) {
            int r0 = bm + wm + mt * 16 + tg;
            float2 v0, v1;
            v0.x = acc[mt][nt][0] + b2.x; v0.y = acc[mt][nt][1] + b2.y;
            v1.x = acc[mt][nt][2] + b2.x; v1.y = acc[mt][nt][3] + b2.y;
            if (RELU) {
                v0.x = fmaxf(v0.x, 0.f); v0.y = fmaxf(v0.y, 0.f);
                v1.x = fmaxf(v1.x, 0.f); v1.y = fmaxf(v1.y, 0.f);
            }
            size_t o0 = (size_t)r0 * 256 + col, o1 = o0 + 8 * 256;
            if (!SPLIT) {
                *(float2*)(Cf + o0) = v0;
                *(float2*)(Cf + o1) = v1;
            } else {
                split_store2(Ch + o0, Cl + o0, v0);
                split_store2(Ch + o1, Cl + o1, v1);
            }
        }
    }
}

// ---------------- z[r] = h2[r mod B] * h2[B + r], split to bf16 hi/lo ----------------
__global__ void build_z() {
    int r = blockIdx.x, c = threadIdx.x;   // grid 8192, block 64
    const float4* s = (const float4*)(g_h2 + (size_t)(r & (Bsz - 1)) * HID);
    const float4* o = (const float4*)(g_h2 + (size_t)(Bsz + r) * HID);
    float4 a = s[c], b = o[c];
    float4 v = make_float4(a.x * b.x, a.y * b.y, a.z * b.z, a.w * b.w);
    split_store4(g_zh + (size_t)r * HID + 4 * c, g_zl + (size_t)r * HID + 4 * c, v);
}

// ---------------- scores = z2 @ Wp3 + bp3 ----------------
__global__ void final_dot(const float* __restrict__ Wp3, const float* __restrict__ bp3,
                          float* __restrict__ out) {
    int gw   = (blockIdx.x * blockDim.x + threadIdx.x) >> 5;
    int lane = threadIdx.x & 31;
    const float4* z = (const float4*)(g_z2 + (size_t)gw * HID);
    const float4* w = (const float4*)Wp3;
    float4 z0 = z[lane], z1 = z[32 + lane];
    float4 w0 = __ldg(w + lane), w1 = __ldg(w + 32 + lane);
    float s = z0.x * w0.x + z0.y * w0.y + z0.z * w0.z + z0.w * w0.w
            + z1.x * w1.x + z1.y * w1.y + z1.z * w1.z + z1.w * w1.w;
    #pragma unroll
    for (int o = 16; o; o >>= 1) s += __shfl_xor_sync(0xffffffffu, s, o);
    if (lane == 0) out[gw] = s + bp3[0];
}

extern "C" void kernel_launch(void* const* d_in, const int* in_sizes, int n_in,
                              void* d_out, int out_size) {
    const float* node_feat = (const float*)d_in[0];
    const int*   gids0     = (const int*)d_in[1];
    const int*   nidx0     = (const int*)d_in[2];
    const int*   nidx1     = (const int*)d_in[3];
    const float* Ws0 = (const float*)d_in[4];
    const float* Wn0 = (const float*)d_in[5];
    const float* b0  = (const float*)d_in[6];
    const float* Ws1 = (const float*)d_in[7];
    const float* Wn1 = (const float*)d_in[8];
    const float* b1  = (const float*)d_in[9];
    const float* Wp1 = (const float*)d_in[10];
    const float* bp1 = (const float*)d_in[11];
    const float* Wp2 = (const float*)d_in[12];
    const float* bp2 = (const float*)d_in[13];
    const float* Wp3 = (const float*)d_in[14];
    const float* bp3 = (const float*)d_in[15];
    float* out = (float*)d_out;

    cudaFuncSetAttribute(hgemm<true,  false>, cudaFuncAttributeMaxDynamicSharedMemorySize, GEMM_SMEM);
    cudaFuncSetAttribute(hgemm<false, false>, cudaFuncAttributeMaxDynamicSharedMemorySize, GEMM_SMEM);
    cudaFuncSetAttribute(hgemm<true,  true >, cudaFuncAttributeMaxDynamicSharedMemorySize, GEMM_SMEM);

    __nv_bfloat16 *u0h, *u0l, *u1h, *u1l, *zh, *zl, *z1h, *z1l;
    __nv_bfloat16 *W0h, *W0l, *W1h, *W1l, *P1h, *P1l, *P2h, *P2l;
    float *h0, *h2, *z2;
    cudaGetSymbolAddress((void**)&u0h, g_u0h); cudaGetSymbolAddress((void**)&u0l, g_u0l);
    cudaGetSymbolAddress((void**)&u1h, g_u1h); cudaGetSymbolAddress((void**)&u1l, g_u1l);
    cudaGetSymbolAddress((void**)&zh,  g_zh);  cudaGetSymbolAddress((void**)&zl,  g_zl);
    cudaGetSymbolAddress((void**)&z1h, g_z1h); cudaGetSymbolAddress((void**)&z1l, g_z1l);
    cudaGetSymbolAddress((void**)&W0h, g_W0h); cudaGetSymbolAddress((void**)&W0l, g_W0l);
    cudaGetSymbolAddress((void**)&W1h, g_W1h); cudaGetSymbolAddress((void**)&W1l, g_W1l);
    cudaGetSymbolAddress((void**)&P1h, g_P1h); cudaGetSymbolAddress((void**)&P1l, g_P1l);
    cudaGetSymbolAddress((void**)&P2h, g_P2h); cudaGetSymbolAddress((void**)&P2l, g_P2l);
    cudaGetSymbolAddress((void**)&h0,  g_h0);  cudaGetSymbolAddress((void**)&h2,  g_h2);
    cudaGetSymbolAddress((void**)&z2,  g_z2);

    pack_weights<<<HID, HID>>>(Ws0, Wn0, Ws1, Wn1, Wp1, Wp2);

    // layer 0
    gather_agg0<<<N1n / 8, 256>>>(node_feat, gids0, nidx0);
    hgemm<true, false><<<dim3(2, N1n / 128), 256, GEMM_SMEM>>>(
        u0h, u0l, W0h, W0l, b0, h0, nullptr, nullptr, 2 * IN_DIM);

    // layer 1
    gather_agg1<<<N2n / 8, 256>>>(nidx1);
    hgemm<false, false><<<dim3(2, N2n / 128), 256, GEMM_SMEM>>>(
        u1h, u1l, W1h, W1l, b1, h2, nullptr, nullptr, 2 * HID);

    // edge MLP
    build_z<<<ZROWS, 64>>>();
    hgemm<true, true><<<dim3(2, ZROWS / 128), 256, GEMM_SMEM>>>(
        zh, zl, P1h, P1l, bp1, nullptr, z1h, z1l, HID);
    hgemm<true, false><<<dim3(2, ZROWS / 128), 256, GEMM_SMEM>>>(
        z1h, z1l, P2h, P2l, bp2, z2, nullptr, nullptr, HID);
    final_dot<<<ZROWS / 8, 256>>>(Wp3, bp3, out);
}

// round 5
// speedup vs baseline: 2.3195x; 1.2449x over previous
#include <cuda_runtime.h>
#include <cuda_bf16.h>
#include <cstdint>

#define FAN 10
constexpr int IN_DIM = 128;
constexpr int HID    = 256;
constexpr int Bsz    = 4096;
constexpr int N2n    = 3 * Bsz;       // 12288
constexpr int N1n    = N2n * FAN;     // 122880
constexpr int ZROWS  = 2 * Bsz;       // 8192

// ---------------- scratch (device globals: allocation-free) ----------------
__device__ __align__(16) __nv_bfloat16 g_u0h[(size_t)N1n * HID];
__device__ __align__(16) __nv_bfloat16 g_u0l[(size_t)N1n * HID];
__device__ __align__(16) float         g_h0 [(size_t)N1n * HID];
__device__ __align__(16) __nv_bfloat16 g_u1h[(size_t)N2n * 2 * HID];
__device__ __align__(16) __nv_bfloat16 g_u1l[(size_t)N2n * 2 * HID];
__device__ __align__(16) float         g_h2 [(size_t)N2n * HID];
__device__ __align__(16) __nv_bfloat16 g_zh [(size_t)ZROWS * HID];
__device__ __align__(16) __nv_bfloat16 g_zl [(size_t)ZROWS * HID];
__device__ __align__(16) __nv_bfloat16 g_z1h[(size_t)ZROWS * HID];
__device__ __align__(16) __nv_bfloat16 g_z1l[(size_t)ZROWS * HID];
__device__ __align__(16) float         g_z2 [(size_t)ZROWS * HID];
// transposed bf16 hi/lo weights: [N=256, K]
__device__ __align__(16) __nv_bfloat16 g_W0h[HID * HID],     g_W0l[HID * HID];
__device__ __align__(16) __nv_bfloat16 g_W1h[HID * 2 * HID], g_W1l[HID * 2 * HID];
__device__ __align__(16) __nv_bfloat16 g_P1h[HID * HID],     g_P1l[HID * HID];
__device__ __align__(16) __nv_bfloat16 g_P2h[HID * HID],     g_P2l[HID * HID];
// row compaction: only h0 rows referenced by layer 1 are computed
__device__ int g_cnt;                 // M' = number of live rows
__device__ int g_flags[N1n];
__device__ int g_newid[N1n];          // original row -> compacted row
__device__ int g_orig [N1n];          // compacted row -> original row

// ---------------- PTX helpers (base sm_103-safe: mma.sync / ldmatrix / cp.async) ----
__device__ __forceinline__ uint32_t smem_u32(const void* p) {
    uint32_t a;
    asm("{ .reg .u64 t; cvta.to.shared.u64 t, %1; cvt.u32.u64 %0, t; }" : "=r"(a) : "l"(p));
    return a;
}
__device__ __forceinline__ void mma16816(float* d, const uint32_t* a, const uint32_t* b) {
    asm volatile("mma.sync.aligned.m16n8k16.row.col.f32.bf16.bf16.f32 "
                 "{%0,%1,%2,%3}, {%4,%5,%6,%7}, {%8,%9}, {%0,%1,%2,%3};"
                 : "+f"(d[0]), "+f"(d[1]), "+f"(d[2]), "+f"(d[3])
                 : "r"(a[0]), "r"(a[1]), "r"(a[2]), "r"(a[3]), "r"(b[0]), "r"(b[1]));
}
__device__ __forceinline__ void ldsm4(uint32_t* r, uint32_t addr) {
    asm volatile("ldmatrix.sync.aligned.m8n8.x4.shared.b16 {%0,%1,%2,%3}, [%4];"
                 : "=r"(r[0]), "=r"(r[1]), "=r"(r[2]), "=r"(r[3]) : "r"(addr));
}
#define CP16(dst, src) asm volatile("cp.async.cg.shared.global [%0], [%1], 16;" :: "r"(dst), "l"(src))
#define CP_COMMIT()    asm volatile("cp.async.commit_group;" ::: "memory")
#define CP_WAIT1()     asm volatile("cp.async.wait_group 1;" ::: "memory")
#define CP_WAIT0()     asm volatile("cp.async.wait_group 0;" ::: "memory")

// ---------------- bf16 hi/lo split helpers ----------------
__device__ __forceinline__ __nv_bfloat16 bf_hi(float v) { return __float2bfloat16_rn(v); }
__device__ __forceinline__ void split_store4(__nv_bfloat16* ph, __nv_bfloat16* pl, float4 v) {
    __nv_bfloat16 hx = bf_hi(v.x), hy = bf_hi(v.y), hz = bf_hi(v.z), hw = bf_hi(v.w);
    __nv_bfloat162 h01, h23, l01, l23;
    h01.x = hx; h01.y = hy; h23.x = hz; h23.y = hw;
    l01.x = bf_hi(v.x - __bfloat162float(hx)); l01.y = bf_hi(v.y - __bfloat162float(hy));
    l23.x = bf_hi(v.z - __bfloat162float(hz)); l23.y = bf_hi(v.w - __bfloat162float(hw));
    uint2 H, L;
    H.x = *(unsigned*)&h01; H.y = *(unsigned*)&h23;
    L.x = *(unsigned*)&l01; L.y = *(unsigned*)&l23;
    *(uint2*)ph = H; *(uint2*)pl = L;
}
__device__ __forceinline__ void split_store2(__nv_bfloat16* ph, __nv_bfloat16* pl, float2 v) {
    __nv_bfloat16 hx = bf_hi(v.x), hy = bf_hi(v.y);
    __nv_bfloat162 h, l;
    h.x = hx; h.y = hy;
    l.x = bf_hi(v.x - __bfloat162float(hx)); l.y = bf_hi(v.y - __bfloat162float(hy));
    *(unsigned*)ph = *(unsigned*)&h;
    *(unsigned*)pl = *(unsigned*)&l;
}

// ---------------- weight packing (transposed bf16 hi/lo) ----------------
__global__ void pack_weights(const float* __restrict__ Ws0, const float* __restrict__ Wn0,
                             const float* __restrict__ Ws1, const float* __restrict__ Wn1,
                             const float* __restrict__ Wp1, const float* __restrict__ Wp2) {
    int n = blockIdx.x, k = threadIdx.x;   // 256 x 256
    auto split1 = [](float v, __nv_bfloat16* h, __nv_bfloat16* l) {
        __nv_bfloat16 hb = __float2bfloat16_rn(v);
        *h = hb; *l = __float2bfloat16_rn(v - __bfloat162float(hb));
    };
    float w0 = (k < IN_DIM) ? Ws0[k * HID + n] : Wn0[(k - IN_DIM) * HID + n];
    split1(w0, &g_W0h[n * HID + k], &g_W0l[n * HID + k]);
    split1(Wp1[k * HID + n], &g_P1h[n * HID + k], &g_P1l[n * HID + k]);
    split1(Wp2[k * HID + n], &g_P2h[n * HID + k], &g_P2l[n * HID + k]);
    split1(Ws1[k * HID + n], &g_W1h[n * 2 * HID + k],       &g_W1l[n * 2 * HID + k]);
    split1(Wn1[k * HID + n], &g_W1h[n * 2 * HID + k + HID], &g_W1l[n * 2 * HID + k + HID]);
}

// ---------------- compaction: which h0 rows does layer 1 actually read? ----------------
__global__ void init_flags() {
    int i = blockIdx.x * blockDim.x + threadIdx.x;          // grid 480 x 256
    g_flags[i] = (i < N2n) ? 1 : 0;                         // self rows always live
    if (i == 0) g_cnt = 0;
}
__global__ void mark_rows(const int* __restrict__ nidx1) {
    int e = blockIdx.x * blockDim.x + threadIdx.x;          // grid 480 x 256 (N2n*FAN)
    g_flags[nidx1[e]] = 1;
}
__global__ void compact_rows() {
    int i = blockIdx.x * blockDim.x + threadIdx.x;          // grid 480 x 256
    if (g_flags[i]) {
        int p = atomicAdd(&g_cnt, 1);                       // order-invariant downstream
        g_orig[p] = i;
        g_newid[i] = p;
    }
}

// ---------------- layer0 gather + mean -> bf16 hi/lo (compacted rows only) ----------------
__global__ void gather_agg0(const float* __restrict__ nf, const int* __restrict__ gids,
                            const int* __restrict__ nidx) {
    int gw   = (blockIdx.x * blockDim.x + threadIdx.x) >> 5; // compacted row id
    int lane = threadIdx.x & 31;
    if (gw >= __ldg(&g_cnt)) return;
    int row = __ldg(&g_orig[gw]);                            // original dst row

    int idx_l = 0;
    if (lane < FAN)       idx_l = gids[nidx[(size_t)row * FAN + lane]];
    else if (lane == FAN) idx_l = gids[row];

    float4 v[FAN];
    #pragma unroll
    for (int k = 0; k < FAN; k++) {
        int g = __shfl_sync(0xffffffffu, idx_l, k);
        v[k] = __ldg((const float4*)nf + (size_t)g * (IN_DIM / 4) + lane);
    }
    int gs = __shfl_sync(0xffffffffu, idx_l, FAN);
    float4 s = __ldg((const float4*)nf + (size_t)gs * (IN_DIM / 4) + lane);

    float4 a = make_float4(0.f, 0.f, 0.f, 0.f);
    #pragma unroll
    for (int k = 0; k < FAN; k++) { a.x += v[k].x; a.y += v[k].y; a.z += v[k].z; a.w += v[k].w; }
    const float inv = 1.0f / FAN;
    a.x *= inv; a.y *= inv; a.z *= inv; a.w *= inv;

    size_t rb = (size_t)gw * HID;
    split_store4(g_u0h + rb + 4 * lane,       g_u0l + rb + 4 * lane,       s);
    split_store4(g_u0h + rb + 128 + 4 * lane, g_u0l + rb + 128 + 4 * lane, a);
}

// ---------------- layer1 gather + mean over compacted g_h0 -> bf16 hi/lo ----------------
__global__ void gather_agg1(const int* __restrict__ nidx) {
    int gw   = (blockIdx.x * blockDim.x + threadIdx.x) >> 5;
    int lane = threadIdx.x & 31;

    int idx_l = 0;
    if (lane < FAN)       idx_l = __ldg(&g_newid[nidx[(size_t)gw * FAN + lane]]);
    else if (lane == FAN) idx_l = __ldg(&g_newid[gw]);

    float4 a0 = make_float4(0.f, 0.f, 0.f, 0.f), a1 = a0;
    #pragma unroll
    for (int k = 0; k < FAN; k++) {
        int j = __shfl_sync(0xffffffffu, idx_l, k);
        const float4* row = (const float4*)g_h0 + (size_t)j * (HID / 4);
        float4 v0 = __ldg(row + lane);
        float4 v1 = __ldg(row + 32 + lane);
        a0.x += v0.x; a0.y += v0.y; a0.z += v0.z; a0.w += v0.w;
        a1.x += v1.x; a1.y += v1.y; a1.z += v1.z; a1.w += v1.w;
    }
    int js = __shfl_sync(0xffffffffu, idx_l, FAN);
    const float4* srow = (const float4*)g_h0 + (size_t)js * (HID / 4);
    float4 s0 = __ldg(srow + lane), s1 = __ldg(srow + 32 + lane);

    const float inv = 1.0f / FAN;
    a0.x *= inv; a0.y *= inv; a0.z *= inv; a0.w *= inv;
    a1.x *= inv; a1.y *= inv; a1.z *= inv; a1.w *= inv;

    size_t rb = (size_t)gw * (2 * HID);
    split_store4(g_u1h + rb + 4 * lane,       g_u1l + rb + 4 * lane,       s0);
    split_store4(g_u1h + rb + 128 + 4 * lane, g_u1l + rb + 128 + 4 * lane, s1);
    split_store4(g_u1h + rb + 256 + 4 * lane, g_u1l + rb + 256 + 4 * lane, a0);
    split_store4(g_u1h + rb + 384 + 4 * lane, g_u1l + rb + 384 + 4 * lane, a1);
}

// ---------------- HMMA GEMM: C[M,256] = act(A[M,K] @ W[K,256] + bias) ----------------
// A as bf16 hi/lo [M,K] row-major; W as transposed bf16 hi/lo Bt[256,K].
// 3-pass split: D += Ah*Bh + Ah*Bl + Al*Bh (fp32 accum via mma.sync.m16n8k16).
// BM=128, BN=128, BK=32; 256 threads = 8 warps (2m x 4n), warp tile 64x32.
// smem: 2 stages x (Ah 8K | Al 8K | Bh 8K | Bl 8K) = 64 KB dynamic.
// Optional Mlim: device row-count; CTAs whose tile starts past it exit.
constexpr int GEMM_SMEM = 65536;

template <bool RELU, bool SPLIT>
__global__ void __launch_bounds__(256, 1) hgemm(
    const __nv_bfloat16* __restrict__ Ah, const __nv_bfloat16* __restrict__ Al,
    const __nv_bfloat16* __restrict__ Bh, const __nv_bfloat16* __restrict__ Bl,
    const float* __restrict__ bias,
    float* __restrict__ Cf, __nv_bfloat16* __restrict__ Ch, __nv_bfloat16* __restrict__ Cl,
    int K, const int* Mlim)
{
    extern __shared__ char sm[];
    const int bm = blockIdx.y * 128, bn = blockIdx.x * 128;
    if (Mlim != nullptr && bm >= __ldg(Mlim)) return;
    const uint32_t sb = smem_u32(sm);
    const int tid = threadIdx.x, lane = tid & 31, wid = tid >> 5;
    const int wm = (wid >> 2) * 64, wn = (wid & 3) * 32;
    const int nCh = K >> 5;                 // BK=32 chunks

    // smem tile offset: [128 rows][4 x 16B chunks], xor-swizzled chunk
    auto swo = [](int r, int c) -> uint32_t { return (uint32_t)(r * 64 + ((c ^ ((r >> 1) & 3)) << 4)); };

    auto load_stage = [&](int stage, int kc) {
        const uint32_t base = sb + stage * 32768;
        #pragma unroll
        for (int i = 0; i < 2; i++) {
            int q = tid + i * 256;          // 512 chunks per tile
            int r = q >> 2, c = q & 3;
            uint32_t so = swo(r, c);
            size_t ga = (size_t)(bm + r) * K + kc * 32 + c * 8;
            size_t gb = (size_t)(bn + r) * K + kc * 32 + c * 8;
            CP16(base +         so, Ah + ga);
            CP16(base +  8192 + so, Al + ga);
            CP16(base + 16384 + so, Bh + gb);
            CP16(base + 24576 + so, Bl + gb);
        }
    };

    float acc[4][4][4];
    #pragma unroll
    for (int i = 0; i < 4; i++)
        #pragma unroll
        for (int j = 0; j < 4; j++)
            #pragma unroll
            for (int k = 0; k < 4; k++) acc[i][j][k] = 0.f;

    load_stage(0, 0);
    CP_COMMIT();

    for (int kc = 0; kc < nCh; kc++) {
        if (kc + 1 < nCh) { load_stage((kc + 1) & 1, kc + 1); CP_COMMIT(); CP_WAIT1(); }
        else              { CP_WAIT0(); }
        __syncthreads();

        const uint32_t base = sb + (kc & 1) * 32768;
        #pragma unroll
        for (int ks = 0; ks < 2; ks++) {
            uint32_t aH[4][4], aL[4][4], bH[2][4], bL[2][4];
            #pragma unroll
            for (int mt = 0; mt < 4; mt++) {
                int row = wm + mt * 16 + (lane & 15);
                int kch = 2 * ks + (lane >> 4);
                uint32_t so = swo(row, kch);
                ldsm4(aH[mt], base + so);
                ldsm4(aL[mt], base + 8192 + so);
            }
            #pragma unroll
            for (int p = 0; p < 2; p++) {
                int row = wn + p * 16 + (lane & 7) + ((lane >> 4) << 3);
                int kch = 2 * ks + ((lane >> 3) & 1);
                uint32_t so = swo(row, kch);
                ldsm4(bH[p], base + 16384 + so);
                ldsm4(bL[p], base + 24576 + so);
            }
            #pragma unroll
            for (int mt = 0; mt < 4; mt++) {
                #pragma unroll
                for (int nt = 0; nt < 4; nt++) {
                    const uint32_t* bh = &bH[nt >> 1][(nt & 1) * 2];
                    const uint32_t* bl = &bL[nt >> 1][(nt & 1) * 2];
                    mma16816(acc[mt][nt], aH[mt], bh);
                    mma16816(acc[mt][nt], aH[mt], bl);
                    mma16816(acc[mt][nt], aL[mt], bh);
                }
            }
        }
        __syncthreads();
    }

    // epilogue: direct float2 stores (+bias, act)
    const int tg = lane >> 2, tt = lane & 3;
    #pragma unroll
    for (int nt = 0; nt < 4; nt++) {
        int col = bn + wn + nt * 8 + 2 * tt;
        float2 b2 = *(const float2*)(bias + col);
        #pragma unroll
        for (int mt = 0; mt < 4; mt++) {
            int r0 = bm + wm + mt * 16 + tg;
            float2 v0, v1;
            v0.x = acc[mt][nt][0] + b2.x; v0.y = acc[mt][nt][1] + b2.y;
            v1.x = acc[mt][nt][2] + b2.x; v1.y = acc[mt][nt][3] + b2.y;
            if (RELU) {
                v0.x = fmaxf(v0.x, 0.f); v0.y = fmaxf(v0.y, 0.f);
                v1.x = fmaxf(v1.x, 0.f); v1.y = fmaxf(v1.y, 0.f);
            }
            size_t o0 = (size_t)r0 * 256 + col, o1 = o0 + 8 * 256;
            if (!SPLIT) {
                *(float2*)(Cf + o0) = v0;
                *(float2*)(Cf + o1) = v1;
            } else {
                split_store2(Ch + o0, Cl + o0, v0);
                split_store2(Ch + o1, Cl + o1, v1);
            }
        }
    }
}

// ---------------- z[r] = h2[r mod B] * h2[B + r], split to bf16 hi/lo ----------------
__global__ void build_z() {
    int r = blockIdx.x, c = threadIdx.x;   // grid 8192, block 64
    const float4* s = (const float4*)(g_h2 + (size_t)(r & (Bsz - 1)) * HID);
    const float4* o = (const float4*)(g_h2 + (size_t)(Bsz + r) * HID);
    float4 a = s[c], b = o[c];
    float4 v = make_float4(a.x * b.x, a.y * b.y, a.z * b.z, a.w * b.w);
    split_store4(g_zh + (size_t)r * HID + 4 * c, g_zl + (size_t)r * HID + 4 * c, v);
}

// ---------------- scores = z2 @ Wp3 + bp3 ----------------
__global__ void final_dot(const float* __restrict__ Wp3, const float* __restrict__ bp3,
                          float* __restrict__ out) {
    int gw   = (blockIdx.x * blockDim.x + threadIdx.x) >> 5;
    int lane = threadIdx.x & 31;
    const float4* z = (const float4*)(g_z2 + (size_t)gw * HID);
    const float4* w = (const float4*)Wp3;
    float4 z0 = z[lane], z1 = z[32 + lane];
    float4 w0 = __ldg(w + lane), w1 = __ldg(w + 32 + lane);
    float s = z0.x * w0.x + z0.y * w0.y + z0.z * w0.z + z0.w * w0.w
            + z1.x * w1.x + z1.y * w1.y + z1.z * w1.z + z1.w * w1.w;
    #pragma unroll
    for (int o = 16; o; o >>= 1) s += __shfl_xor_sync(0xffffffffu, s, o);
    if (lane == 0) out[gw] = s + bp3[0];
}

extern "C" void kernel_launch(void* const* d_in, const int* in_sizes, int n_in,
                              void* d_out, int out_size) {
    const float* node_feat = (const float*)d_in[0];
    const int*   gids0     = (const int*)d_in[1];
    const int*   nidx0     = (const int*)d_in[2];
    const int*   nidx1     = (const int*)d_in[3];
    const float* Ws0 = (const float*)d_in[4];
    const float* Wn0 = (const float*)d_in[5];
    const float* b0  = (const float*)d_in[6];
    const float* Ws1 = (const float*)d_in[7];
    const float* Wn1 = (const float*)d_in[8];
    const float* b1  = (const float*)d_in[9];
    const float* Wp1 = (const float*)d_in[10];
    const float* bp1 = (const float*)d_in[11];
    const float* Wp2 = (const float*)d_in[12];
    const float* bp2 = (const float*)d_in[13];
    const float* Wp3 = (const float*)d_in[14];
    const float* bp3 = (const float*)d_in[15];
    float* out = (float*)d_out;

    cudaFuncSetAttribute(hgemm<true,  false>, cudaFuncAttributeMaxDynamicSharedMemorySize, GEMM_SMEM);
    cudaFuncSetAttribute(hgemm<false, false>, cudaFuncAttributeMaxDynamicSharedMemorySize, GEMM_SMEM);
    cudaFuncSetAttribute(hgemm<true,  true >, cudaFuncAttributeMaxDynamicSharedMemorySize, GEMM_SMEM);

    __nv_bfloat16 *u0h, *u0l, *u1h, *u1l, *zh, *zl, *z1h, *z1l;
    __nv_bfloat16 *W0h, *W0l, *W1h, *W1l, *P1h, *P1l, *P2h, *P2l;
    float *h0, *h2, *z2;
    int* cnt;
    cudaGetSymbolAddress((void**)&u0h, g_u0h); cudaGetSymbolAddress((void**)&u0l, g_u0l);
    cudaGetSymbolAddress((void**)&u1h, g_u1h); cudaGetSymbolAddress((void**)&u1l, g_u1l);
    cudaGetSymbolAddress((void**)&zh,  g_zh);  cudaGetSymbolAddress((void**)&zl,  g_zl);
    cudaGetSymbolAddress((void**)&z1h, g_z1h); cudaGetSymbolAddress((void**)&z1l, g_z1l);
    cudaGetSymbolAddress((void**)&W0h, g_W0h); cudaGetSymbolAddress((void**)&W0l, g_W0l);
    cudaGetSymbolAddress((void**)&W1h, g_W1h); cudaGetSymbolAddress((void**)&W1l, g_W1l);
    cudaGetSymbolAddress((void**)&P1h, g_P1h); cudaGetSymbolAddress((void**)&P1l, g_P1l);
    cudaGetSymbolAddress((void**)&P2h, g_P2h); cudaGetSymbolAddress((void**)&P2l, g_P2l);
    cudaGetSymbolAddress((void**)&h0,  g_h0);  cudaGetSymbolAddress((void**)&h2,  g_h2);
    cudaGetSymbolAddress((void**)&z2,  g_z2);  cudaGetSymbolAddress((void**)&cnt, g_cnt);

    pack_weights<<<HID, HID>>>(Ws0, Wn0, Ws1, Wn1, Wp1, Wp2);

    // row liveness: mark h0 rows read by layer 1, compact them
    init_flags<<<N1n / 256, 256>>>();
    mark_rows<<<(N2n * FAN) / 256, 256>>>(nidx1);
    compact_rows<<<N1n / 256, 256>>>();

    // layer 0 (compacted rows only; CTAs past M' early-exit)
    gather_agg0<<<N1n / 8, 256>>>(node_feat, gids0, nidx0);
    hgemm<true, false><<<dim3(2, N1n / 128), 256, GEMM_SMEM>>>(
        u0h, u0l, W0h, W0l, b0, h0, nullptr, nullptr, 2 * IN_DIM, cnt);

    // layer 1
    gather_agg1<<<N2n / 8, 256>>>(nidx1);
    hgemm<false, false><<<dim3(2, N2n / 128), 256, GEMM_SMEM>>>(
        u1h, u1l, W1h, W1l, b1, h2, nullptr, nullptr, 2 * HID, nullptr);

    // edge MLP
    build_z<<<ZROWS, 64>>>();
    hgemm<true, true><<<dim3(2, ZROWS / 128), 256, GEMM_SMEM>>>(
        zh, zl, P1h, P1l, bp1, nullptr, z1h, z1l, HID, nullptr);
    hgemm<true, false><<<dim3(2, ZROWS / 128), 256, GEMM_SMEM>>>(
        z1h, z1l, P2h, P2l, bp2, z2, nullptr, nullptr, HID, nullptr);
    final_dot<<<ZROWS / 8, 256>>>(Wp3, bp3, out);
}

// round 6
// speedup vs baseline: 2.3259x; 1.0028x over previous
#include <cuda_runtime.h>
#include <cuda_bf16.h>
#include <cstdint>

#define FAN 10
constexpr int IN_DIM = 128;
constexpr int HID    = 256;
constexpr int Bsz    = 4096;
constexpr int N2n    = 3 * Bsz;       // 12288
constexpr int N1n    = N2n * FAN;     // 122880
constexpr int ZROWS  = 2 * Bsz;       // 8192

// ---------------- scratch (device globals: allocation-free) ----------------
__device__ __align__(16) __nv_bfloat16 g_u0h[(size_t)N1n * HID];
__device__ __align__(16) __nv_bfloat16 g_u0l[(size_t)N1n * HID];
__device__ __align__(16) float         g_h0 [(size_t)N1n * HID];
__device__ __align__(16) __nv_bfloat16 g_u1h[(size_t)N2n * 2 * HID];
__device__ __align__(16) __nv_bfloat16 g_u1l[(size_t)N2n * 2 * HID];
__device__ __align__(16) float         g_h2 [(size_t)N2n * HID];
__device__ __align__(16) __nv_bfloat16 g_zh [(size_t)ZROWS * HID];
__device__ __align__(16) __nv_bfloat16 g_zl [(size_t)ZROWS * HID];
__device__ __align__(16) __nv_bfloat16 g_z1h[(size_t)ZROWS * HID];
__device__ __align__(16) __nv_bfloat16 g_z1l[(size_t)ZROWS * HID];
__device__ __align__(16) float         g_z2 [(size_t)ZROWS * HID];
// transposed bf16 hi/lo weights: [N=256, K]
__device__ __align__(16) __nv_bfloat16 g_W0h[HID * HID],     g_W0l[HID * HID];
__device__ __align__(16) __nv_bfloat16 g_W1h[HID * 2 * HID], g_W1l[HID * 2 * HID];
__device__ __align__(16) __nv_bfloat16 g_P1h[HID * HID],     g_P1l[HID * HID];
__device__ __align__(16) __nv_bfloat16 g_P2h[HID * HID],     g_P2l[HID * HID];
// row compaction: only h0 rows referenced by layer 1 are computed
__device__ int g_cnt;                 // M' = number of live rows
__device__ int g_flags[N1n];
__device__ int g_newid[N1n];          // original row -> compacted row
__device__ int g_orig [N1n];          // compacted row -> original row

// ---------------- PTX helpers (base sm_103-safe: mma.sync / ldmatrix / cp.async) ----
__device__ __forceinline__ uint32_t smem_u32(const void* p) {
    uint32_t a;
    asm("{ .reg .u64 t; cvta.to.shared.u64 t, %1; cvt.u32.u64 %0, t; }" : "=r"(a) : "l"(p));
    return a;
}
__device__ __forceinline__ void mma16816(float* d, const uint32_t* a, const uint32_t* b) {
    asm volatile("mma.sync.aligned.m16n8k16.row.col.f32.bf16.bf16.f32 "
                 "{%0,%1,%2,%3}, {%4,%5,%6,%7}, {%8,%9}, {%0,%1,%2,%3};"
                 : "+f"(d[0]), "+f"(d[1]), "+f"(d[2]), "+f"(d[3])
                 : "r"(a[0]), "r"(a[1]), "r"(a[2]), "r"(a[3]), "r"(b[0]), "r"(b[1]));
}
__device__ __forceinline__ void ldsm4(uint32_t* r, uint32_t addr) {
    asm volatile("ldmatrix.sync.aligned.m8n8.x4.shared.b16 {%0,%1,%2,%3}, [%4];"
                 : "=r"(r[0]), "=r"(r[1]), "=r"(r[2]), "=r"(r[3]) : "r"(addr));
}
#define CP16(dst, src) asm volatile("cp.async.cg.shared.global [%0], [%1], 16;" :: "r"(dst), "l"(src))
#define CP_COMMIT()    asm volatile("cp.async.commit_group;" ::: "memory")
#define CP_WAIT1()     asm volatile("cp.async.wait_group 1;" ::: "memory")
#define CP_WAIT0()     asm volatile("cp.async.wait_group 0;" ::: "memory")

// ---------------- bf16 hi/lo split helpers ----------------
__device__ __forceinline__ __nv_bfloat16 bf_hi(float v) { return __float2bfloat16_rn(v); }
__device__ __forceinline__ void split_store4(__nv_bfloat16* ph, __nv_bfloat16* pl, float4 v) {
    __nv_bfloat16 hx = bf_hi(v.x), hy = bf_hi(v.y), hz = bf_hi(v.z), hw = bf_hi(v.w);
    __nv_bfloat162 h01, h23, l01, l23;
    h01.x = hx; h01.y = hy; h23.x = hz; h23.y = hw;
    l01.x = bf_hi(v.x - __bfloat162float(hx)); l01.y = bf_hi(v.y - __bfloat162float(hy));
    l23.x = bf_hi(v.z - __bfloat162float(hz)); l23.y = bf_hi(v.w - __bfloat162float(hw));
    uint2 H, L;
    H.x = *(unsigned*)&h01; H.y = *(unsigned*)&h23;
    L.x = *(unsigned*)&l01; L.y = *(unsigned*)&l23;
    *(uint2*)ph = H; *(uint2*)pl = L;
}
__device__ __forceinline__ void split_store2(__nv_bfloat16* ph, __nv_bfloat16* pl, float2 v) {
    __nv_bfloat16 hx = bf_hi(v.x), hy = bf_hi(v.y);
    __nv_bfloat162 h, l;
    h.x = hx; h.y = hy;
    l.x = bf_hi(v.x - __bfloat162float(hx)); l.y = bf_hi(v.y - __bfloat162float(hy));
    *(unsigned*)ph = *(unsigned*)&h;
    *(unsigned*)pl = *(unsigned*)&l;
}

// ---------------- weight packing (transposed bf16 hi/lo) ----------------
__global__ void pack_weights(const float* __restrict__ Ws0, const float* __restrict__ Wn0,
                             const float* __restrict__ Ws1, const float* __restrict__ Wn1,
                             const float* __restrict__ Wp1, const float* __restrict__ Wp2) {
    int n = blockIdx.x, k = threadIdx.x;   // 256 x 256
    auto split1 = [](float v, __nv_bfloat16* h, __nv_bfloat16* l) {
        __nv_bfloat16 hb = __float2bfloat16_rn(v);
        *h = hb; *l = __float2bfloat16_rn(v - __bfloat162float(hb));
    };
    float w0 = (k < IN_DIM) ? Ws0[k * HID + n] : Wn0[(k - IN_DIM) * HID + n];
    split1(w0, &g_W0h[n * HID + k], &g_W0l[n * HID + k]);
    split1(Wp1[k * HID + n], &g_P1h[n * HID + k], &g_P1l[n * HID + k]);
    split1(Wp2[k * HID + n], &g_P2h[n * HID + k], &g_P2l[n * HID + k]);
    split1(Ws1[k * HID + n], &g_W1h[n * 2 * HID + k],       &g_W1l[n * 2 * HID + k]);
    split1(Wn1[k * HID + n], &g_W1h[n * 2 * HID + k + HID], &g_W1l[n * 2 * HID + k + HID]);
}

// ---------------- compaction: which h0 rows does layer 1 actually read? ----------------
__global__ void init_flags() {
    int i = blockIdx.x * blockDim.x + threadIdx.x;          // grid 480 x 256
    g_flags[i] = (i < N2n) ? 1 : 0;                         // self rows always live
    if (i == 0) g_cnt = 0;
}
__global__ void mark_rows(const int* __restrict__ nidx1) {
    int e = blockIdx.x * blockDim.x + threadIdx.x;          // grid 480 x 256 (N2n*FAN)
    g_flags[nidx1[e]] = 1;
}
__global__ void compact_rows() {
    int i = blockIdx.x * blockDim.x + threadIdx.x;          // grid 480 x 256
    int lane = threadIdx.x & 31;
    int f = g_flags[i];
    unsigned m = __ballot_sync(0xffffffffu, f);
    int base = 0;
    if (lane == 0 && m) base = atomicAdd(&g_cnt, __popc(m));
    base = __shfl_sync(0xffffffffu, base, 0);
    if (f) {
        int p = base + __popc(m & ((1u << lane) - 1u));
        g_orig[p] = i;
        g_newid[i] = p;
    }
}

// ---------------- layer0 gather + mean -> bf16 hi/lo (compacted rows only) ----------------
// Paired accumulation chains + min-6-blocks bound: trade per-warp MLP for occupancy.
__global__ void __launch_bounds__(256, 6) gather_agg0(
    const float* __restrict__ nf, const int* __restrict__ gids,
    const int* __restrict__ nidx) {
    int gw   = (blockIdx.x * blockDim.x + threadIdx.x) >> 5; // compacted row id
    int lane = threadIdx.x & 31;
    if (gw >= __ldg(&g_cnt)) return;
    int row = __ldg(&g_orig[gw]);                            // original dst row

    int idx_l = 0;
    if (lane < FAN)       idx_l = gids[nidx[(size_t)row * FAN + lane]];
    else if (lane == FAN) idx_l = gids[row];

    int gs = __shfl_sync(0xffffffffu, idx_l, FAN);
    float4 s = __ldg((const float4*)nf + (size_t)gs * (IN_DIM / 4) + lane);

    float4 aa = make_float4(0.f, 0.f, 0.f, 0.f), ab = aa;
    #pragma unroll
    for (int k = 0; k < FAN; k += 2) {
        int ga = __shfl_sync(0xffffffffu, idx_l, k);
        int gb = __shfl_sync(0xffffffffu, idx_l, k + 1);
        float4 va = __ldg((const float4*)nf + (size_t)ga * (IN_DIM / 4) + lane);
        float4 vb = __ldg((const float4*)nf + (size_t)gb * (IN_DIM / 4) + lane);
        aa.x += va.x; aa.y += va.y; aa.z += va.z; aa.w += va.w;
        ab.x += vb.x; ab.y += vb.y; ab.z += vb.z; ab.w += vb.w;
    }
    const float inv = 1.0f / FAN;
    float4 a = make_float4((aa.x + ab.x) * inv, (aa.y + ab.y) * inv,
                           (aa.z + ab.z) * inv, (aa.w + ab.w) * inv);

    size_t rb = (size_t)gw * HID;
    split_store4(g_u0h + rb + 4 * lane,       g_u0l + rb + 4 * lane,       s);
    split_store4(g_u0h + rb + 128 + 4 * lane, g_u0l + rb + 128 + 4 * lane, a);
}

// ---------------- layer1 gather + mean over compacted g_h0 -> bf16 hi/lo ----------------
__global__ void gather_agg1(const int* __restrict__ nidx) {
    int gw   = (blockIdx.x * blockDim.x + threadIdx.x) >> 5;
    int lane = threadIdx.x & 31;

    int idx_l = 0;
    if (lane < FAN)       idx_l = __ldg(&g_newid[nidx[(size_t)gw * FAN + lane]]);
    else if (lane == FAN) idx_l = __ldg(&g_newid[gw]);

    float4 a0 = make_float4(0.f, 0.f, 0.f, 0.f), a1 = a0;
    #pragma unroll
    for (int k = 0; k < FAN; k++) {
        int j = __shfl_sync(0xffffffffu, idx_l, k);
        const float4* row = (const float4*)g_h0 + (size_t)j * (HID / 4);
        float4 v0 = __ldg(row + lane);
        float4 v1 = __ldg(row + 32 + lane);
        a0.x += v0.x; a0.y += v0.y; a0.z += v0.z; a0.w += v0.w;
        a1.x += v1.x; a1.y += v1.y; a1.z += v1.z; a1.w += v1.w;
    }
    int js = __shfl_sync(0xffffffffu, idx_l, FAN);
    const float4* srow = (const float4*)g_h0 + (size_t)js * (HID / 4);
    float4 s0 = __ldg(srow + lane), s1 = __ldg(srow + 32 + lane);

    const float inv = 1.0f / FAN;
    a0.x *= inv; a0.y *= inv; a0.z *= inv; a0.w *= inv;
    a1.x *= inv; a1.y *= inv; a1.z *= inv; a1.w *= inv;

    size_t rb = (size_t)gw * (2 * HID);
    split_store4(g_u1h + rb + 4 * lane,       g_u1l + rb + 4 * lane,       s0);
    split_store4(g_u1h + rb + 128 + 4 * lane, g_u1l + rb + 128 + 4 * lane, s1);
    split_store4(g_u1h + rb + 256 + 4 * lane, g_u1l + rb + 256 + 4 * lane, a0);
    split_store4(g_u1h + rb + 384 + 4 * lane, g_u1l + rb + 384 + 4 * lane, a1);
}

// ---------------- HMMA GEMM: C[M,256] = act(A[M,K] @ W[K,256] + bias) ----------------
// A as bf16 hi/lo [M,K] row-major; W as transposed bf16 hi/lo Bt[256,K].
// 3-pass split: D += Ah*Bh + Ah*Bl + Al*Bh (fp32 accum via mma.sync.m16n8k16).
// BM=128, BN=128, BK=32; 256 threads = 8 warps (2m x 4n), warp tile 64x32.
// smem: 2 stages x (Ah 8K | Al 8K | Bh 8K | Bl 8K) = 64 KB dynamic.
// Optional Mlim: device row-count; CTAs whose tile starts past it exit.
constexpr int GEMM_SMEM = 65536;

template <bool RELU, bool SPLIT>
__global__ void __launch_bounds__(256, 1) hgemm(
    const __nv_bfloat16* __restrict__ Ah, const __nv_bfloat16* __restrict__ Al,
    const __nv_bfloat16* __restrict__ Bh, const __nv_bfloat16* __restrict__ Bl,
    const float* __restrict__ bias,
    float* __restrict__ Cf, __nv_bfloat16* __restrict__ Ch, __nv_bfloat16* __restrict__ Cl,
    int K, const int* Mlim)
{
    extern __shared__ char sm[];
    const int bm = blockIdx.y * 128, bn = blockIdx.x * 128;
    if (Mlim != nullptr && bm >= __ldg(Mlim)) return;
    const uint32_t sb = smem_u32(sm);
    const int tid = threadIdx.x, lane = tid & 31, wid = tid >> 5;
    const int wm = (wid >> 2) * 64, wn = (wid & 3) * 32;
    const int nCh = K >> 5;                 // BK=32 chunks

    // smem tile offset: [128 rows][4 x 16B chunks], xor-swizzled chunk
    auto swo = [](int r, int c) -> uint32_t { return (uint32_t)(r * 64 + ((c ^ ((r >> 1) & 3)) << 4)); };

    auto load_stage = [&](int stage, int kc) {
        const uint32_t base = sb + stage * 32768;
        #pragma unroll
        for (int i = 0; i < 2; i++) {
            int q = tid + i * 256;          // 512 chunks per tile
            int r = q >> 2, c = q & 3;
            uint32_t so = swo(r, c);
            size_t ga = (size_t)(bm + r) * K + kc * 32 + c * 8;
            size_t gb = (size_t)(bn + r) * K + kc * 32 + c * 8;
            CP16(base +         so, Ah + ga);
            CP16(base +  8192 + so, Al + ga);
            CP16(base + 16384 + so, Bh + gb);
            CP16(base + 24576 + so, Bl + gb);
        }
    };

    float acc[4][4][4];
    #pragma unroll
    for (int i = 0; i < 4; i++)
        #pragma unroll
        for (int j = 0; j < 4; j++)
            #pragma unroll
            for (int k = 0; k < 4; k++) acc[i][j][k] = 0.f;

    load_stage(0, 0);
    CP_COMMIT();

    for (int kc = 0; kc < nCh; kc++) {
        if (kc + 1 < nCh) { load_stage((kc + 1) & 1, kc + 1); CP_COMMIT(); CP_WAIT1(); }
        else              { CP_WAIT0(); }
        __syncthreads();

        const uint32_t base = sb + (kc & 1) * 32768;
        #pragma unroll
        for (int ks = 0; ks < 2; ks++) {
            uint32_t aH[4][4], aL[4][4], bH[2][4], bL[2][4];
            #pragma unroll
            for (int mt = 0; mt < 4; mt++) {
                int row = wm + mt * 16 + (lane & 15);
                int kch = 2 * ks + (lane >> 4);
                uint32_t so = swo(row, kch);
                ldsm4(aH[mt], base + so);
                ldsm4(aL[mt], base + 8192 + so);
            }
            #pragma unroll
            for (int p = 0; p < 2; p++) {
                int row = wn + p * 16 + (lane & 7) + ((lane >> 4) << 3);
                int kch = 2 * ks + ((lane >> 3) & 1);
                uint32_t so = swo(row, kch);
                ldsm4(bH[p], base + 16384 + so);
                ldsm4(bL[p], base + 24576 + so);
            }
            #pragma unroll
            for (int mt = 0; mt < 4; mt++) {
                #pragma unroll
                for (int nt = 0; nt < 4; nt++) {
                    const uint32_t* bh = &bH[nt >> 1][(nt & 1) * 2];
                    const uint32_t* bl = &bL[nt >> 1][(nt & 1) * 2];
                    mma16816(acc[mt][nt], aH[mt], bh);
                    mma16816(acc[mt][nt], aH[mt], bl);
                    mma16816(acc[mt][nt], aL[mt], bh);
                }
            }
        }
        __syncthreads();
    }

    // epilogue: direct float2 stores (+bias, act)
    const int tg = lane >> 2, tt = lane & 3;
    #pragma unroll
    for (int nt = 0; nt < 4; nt++) {
        int col = bn + wn + nt * 8 + 2 * tt;
        float2 b2 = *(const float2*)(bias + col);
        #pragma unroll
        for (int mt = 0; mt < 4; mt++) {
            int r0 = bm + wm + mt * 16 + tg;
            float2 v0, v1;
            v0.x = acc[mt][nt][0] + b2.x; v0.y = acc[mt][nt][1] + b2.y;
            v1.x = acc[mt][nt][2] + b2.x; v1.y = acc[mt][nt][3] + b2.y;
            if (RELU) {
                v0.x = fmaxf(v0.x, 0.f); v0.y = fmaxf(v0.y, 0.f);
                v1.x = fmaxf(v1.x, 0.f); v1.y = fmaxf(v1.y, 0.f);
            }
            size_t o0 = (size_t)r0 * 256 + col, o1 = o0 + 8 * 256;
            if (!SPLIT) {
                *(float2*)(Cf + o0) = v0;
                *(float2*)(Cf + o1) = v1;
            } else {
                split_store2(Ch + o0, Cl + o0, v0);
                split_store2(Ch + o1, Cl + o1, v1);
            }
        }
    }
}

// ---------------- z[r] = h2[r mod B] * h2[B + r], split to bf16 hi/lo ----------------
__global__ void build_z() {
    int r = blockIdx.x, c = threadIdx.x;   // grid 8192, block 64
    const float4* s = (const float4*)(g_h2 + (size_t)(r & (Bsz - 1)) * HID);
    const float4* o = (const float4*)(g_h2 + (size_t)(Bsz + r) * HID);
    float4 a = s[c], b = o[c];
    float4 v = make_float4(a.x * b.x, a.y * b.y, a.z * b.z, a.w * b.w);
    split_store4(g_zh + (size_t)r * HID + 4 * c, g_zl + (size_t)r * HID + 4 * c, v);
}

// ---------------- scores = z2 @ Wp3 + bp3 ----------------
__global__ void final_dot(const float* __restrict__ Wp3, const float* __restrict__ bp3,
                          float* __restrict__ out) {
    int gw   = (blockIdx.x * blockDim.x + threadIdx.x) >> 5;
    int lane = threadIdx.x & 31;
    const float4* z = (const float4*)(g_z2 + (size_t)gw * HID);
    const float4* w = (const float4*)Wp3;
    float4 z0 = z[lane], z1 = z[32 + lane];
    float4 w0 = __ldg(w + lane), w1 = __ldg(w + 32 + lane);
    float s = z0.x * w0.x + z0.y * w0.y + z0.z * w0.z + z0.w * w0.w
            + z1.x * w1.x + z1.y * w1.y + z1.z * w1.z + z1.w * w1.w;
    #pragma unroll
    for (int o = 16; o; o >>= 1) s += __shfl_xor_sync(0xffffffffu, s, o);
    if (lane == 0) out[gw] = s + bp3[0];
}

extern "C" void kernel_launch(void* const* d_in, const int* in_sizes, int n_in,
                              void* d_out, int out_size) {
    const float* node_feat = (const float*)d_in[0];
    const int*   gids0     = (const int*)d_in[1];
    const int*   nidx0     = (const int*)d_in[2];
    const int*   nidx1     = (const int*)d_in[3];
    const float* Ws0 = (const float*)d_in[4];
    const float* Wn0 = (const float*)d_in[5];
    const float* b0  = (const float*)d_in[6];
    const float* Ws1 = (const float*)d_in[7];
    const float* Wn1 = (const float*)d_in[8];
    const float* b1  = (const float*)d_in[9];
    const float* Wp1 = (const float*)d_in[10];
    const float* bp1 = (const float*)d_in[11];
    const float* Wp2 = (const float*)d_in[12];
    const float* bp2 = (const float*)d_in[13];
    const float* Wp3 = (const float*)d_in[14];
    const float* bp3 = (const float*)d_in[15];
    float* out = (float*)d_out;

    cudaFuncSetAttribute(hgemm<true,  false>, cudaFuncAttributeMaxDynamicSharedMemorySize, GEMM_SMEM);
    cudaFuncSetAttribute(hgemm<false, false>, cudaFuncAttributeMaxDynamicSharedMemorySize, GEMM_SMEM);
    cudaFuncSetAttribute(hgemm<true,  true >, cudaFuncAttributeMaxDynamicSharedMemorySize, GEMM_SMEM);

    __nv_bfloat16 *u0h, *u0l, *u1h, *u1l, *zh, *zl, *z1h, *z1l;
    __nv_bfloat16 *W0h, *W0l, *W1h, *W1l, *P1h, *P1l, *P2h, *P2l;
    float *h0, *h2, *z2;
    int* cnt;
    cudaGetSymbolAddress((void**)&u0h, g_u0h); cudaGetSymbolAddress((void**)&u0l, g_u0l);
    cudaGetSymbolAddress((void**)&u1h, g_u1h); cudaGetSymbolAddress((void**)&u1l, g_u1l);
    cudaGetSymbolAddress((void**)&zh,  g_zh);  cudaGetSymbolAddress((void**)&zl,  g_zl);
    cudaGetSymbolAddress((void**)&z1h, g_z1h); cudaGetSymbolAddress((void**)&z1l, g_z1l);
    cudaGetSymbolAddress((void**)&W0h, g_W0h); cudaGetSymbolAddress((void**)&W0l, g_W0l);
    cudaGetSymbolAddress((void**)&W1h, g_W1h); cudaGetSymbolAddress((void**)&W1l, g_W1l);
    cudaGetSymbolAddress((void**)&P1h, g_P1h); cudaGetSymbolAddress((void**)&P1l, g_P1l);
    cudaGetSymbolAddress((void**)&P2h, g_P2h); cudaGetSymbolAddress((void**)&P2l, g_P2l);
    cudaGetSymbolAddress((void**)&h0,  g_h0);  cudaGetSymbolAddress((void**)&h2,  g_h2);
    cudaGetSymbolAddress((void**)&z2,  g_z2);  cudaGetSymbolAddress((void**)&cnt, g_cnt);

    // row liveness: mark h0 rows read by layer 1, compact them (launches 1-3)
    init_flags<<<N1n / 256, 256>>>();
    mark_rows<<<(N2n * FAN) / 256, 256>>>(nidx1);
    compact_rows<<<N1n / 256, 256>>>();

    // layer 0 gather — 4th launch (profiled)
    gather_agg0<<<N1n / 8, 256>>>(node_feat, gids0, nidx0);

    // weight packing (only needed from the GEMMs onward)
    pack_weights<<<HID, HID>>>(Ws0, Wn0, Ws1, Wn1, Wp1, Wp2);

    // layer 0 GEMM (compacted rows only; CTAs past M' early-exit)
    hgemm<true, false><<<dim3(2, N1n / 128), 256, GEMM_SMEM>>>(
        u0h, u0l, W0h, W0l, b0, h0, nullptr, nullptr, 2 * IN_DIM, cnt);

    // layer 1
    gather_agg1<<<N2n / 8, 256>>>(nidx1);
    hgemm<false, false><<<dim3(2, N2n / 128), 256, GEMM_SMEM>>>(
        u1h, u1l, W1h, W1l, b1, h2, nullptr, nullptr, 2 * HID, nullptr);

    // edge MLP
    build_z<<<ZROWS, 64>>>();
    hgemm<true, true><<<dim3(2, ZROWS / 128), 256, GEMM_SMEM>>>(
        zh, zl, P1h, P1l, bp1, nullptr, z1h, z1l, HID, nullptr);
    hgemm<true, false><<<dim3(2, ZROWS / 128), 256, GEMM_SMEM>>>(
        z1h, z1l, P2h, P2l, bp2, z2, nullptr, nullptr, HID, nullptr);
    final_dot<<<ZROWS / 8, 256>>>(Wp3, bp3, out);
}

// round 9
// speedup vs baseline: 2.3528x; 1.0116x over previous
#include <cuda_runtime.h>
#include <cuda_bf16.h>
#include <cstdint>

#define FAN 10
constexpr int IN_DIM = 128;
constexpr int HID    = 256;
constexpr int Bsz    = 4096;
constexpr int N2n    = 3 * Bsz;       // 12288
constexpr int N1n    = N2n * FAN;     // 122880
constexpr int ZROWS  = 2 * Bsz;       // 8192

// ---------------- scratch (device globals: allocation-free) ----------------
__device__ __align__(16) __nv_bfloat16 g_u0h[(size_t)N1n * HID];
__device__ __align__(16) __nv_bfloat16 g_u0l[(size_t)N1n * HID];
__device__ __align__(16) float         g_h0 [(size_t)N1n * HID];
__device__ __align__(16) __nv_bfloat16 g_u1h[(size_t)N2n * 2 * HID];
__device__ __align__(16) __nv_bfloat16 g_u1l[(size_t)N2n * 2 * HID];
__device__ __align__(16) float         g_h2 [(size_t)N2n * HID];
__device__ __align__(16) __nv_bfloat16 g_zh [(size_t)ZROWS * HID];
__device__ __align__(16) __nv_bfloat16 g_zl [(size_t)ZROWS * HID];
__device__ __align__(16) __nv_bfloat16 g_z1h[(size_t)ZROWS * HID];
__device__ __align__(16) __nv_bfloat16 g_z1l[(size_t)ZROWS * HID];
__device__ __align__(16) float         g_z2 [(size_t)ZROWS * HID];
// transposed bf16 hi/lo weights: [N=256, K]
__device__ __align__(16) __nv_bfloat16 g_W0h[HID * HID],     g_W0l[HID * HID];
__device__ __align__(16) __nv_bfloat16 g_W1h[HID * 2 * HID], g_W1l[HID * 2 * HID];
__device__ __align__(16) __nv_bfloat16 g_P1h[HID * HID],     g_P1l[HID * HID];
__device__ __align__(16) __nv_bfloat16 g_P2h[HID * HID],     g_P2l[HID * HID];
// row compaction: only h0 rows referenced by layer 1 are computed.
// g_flags is zero-initialized at load; marks are idempotent writes of 1 with
// fixed inputs, so the marked set is identical on every call — no re-zeroing.
__device__ int g_cnt;                 // M' = number of live rows (reset in prep)
__device__ int g_flags[N1n];
__device__ int g_newid[N1n];          // original row -> compacted row
__device__ int g_orig [N1n];          // compacted row -> original row

// ---------------- PTX helpers (base sm_103-safe: mma.sync / ldmatrix / cp.async) ----
__device__ __forceinline__ uint32_t smem_u32(const void* p) {
    uint32_t a;
    asm("{ .reg .u64 t; cvta.to.shared.u64 t, %1; cvt.u32.u64 %0, t; }" : "=r"(a) : "l"(p));
    return a;
}
__device__ __forceinline__ void mma16816(float* d, const uint32_t* a, const uint32_t* b) {
    asm volatile("mma.sync.aligned.m16n8k16.row.col.f32.bf16.bf16.f32 "
                 "{%0,%1,%2,%3}, {%4,%5,%6,%7}, {%8,%9}, {%0,%1,%2,%3};"
                 : "+f"(d[0]), "+f"(d[1]), "+f"(d[2]), "+f"(d[3])
                 : "r"(a[0]), "r"(a[1]), "r"(a[2]), "r"(a[3]), "r"(b[0]), "r"(b[1]));
}
__device__ __forceinline__ void ldsm4(uint32_t* r, uint32_t addr) {
    asm volatile("ldmatrix.sync.aligned.m8n8.x4.shared.b16 {%0,%1,%2,%3}, [%4];"
                 : "=r"(r[0]), "=r"(r[1]), "=r"(r[2]), "=r"(r[3]) : "r"(addr));
}
#define CP16(dst, src) asm volatile("cp.async.cg.shared.global [%0], [%1], 16;" :: "r"(dst), "l"(src))
#define CP_COMMIT()    asm volatile("cp.async.commit_group;" ::: "memory")
#define CP_WAIT1()     asm volatile("cp.async.wait_group 1;" ::: "memory")
#define CP_WAIT0()     asm volatile("cp.async.wait_group 0;" ::: "memory")

// ---------------- bf16 hi/lo split helpers ----------------
__device__ __forceinline__ __nv_bfloat16 bf_hi(float v) { return __float2bfloat16_rn(v); }
__device__ __forceinline__ void split_store4(__nv_bfloat16* ph, __nv_bfloat16* pl, float4 v) {
    __nv_bfloat16 hx = bf_hi(v.x), hy = bf_hi(v.y), hz = bf_hi(v.z), hw = bf_hi(v.w);
    __nv_bfloat162 h01, h23, l01, l23;
    h01.x = hx; h01.y = hy; h23.x = hz; h23.y = hw;
    l01.x = bf_hi(v.x - __bfloat162float(hx)); l01.y = bf_hi(v.y - __bfloat162float(hy));
    l23.x = bf_hi(v.z - __bfloat162float(hz)); l23.y = bf_hi(v.w - __bfloat162float(hw));
    uint2 H, L;
    H.x = *(unsigned*)&h01; H.y = *(unsigned*)&h23;
    L.x = *(unsigned*)&l01; L.y = *(unsigned*)&l23;
    *(uint2*)ph = H; *(uint2*)pl = L;
}
__device__ __forceinline__ void split_store2(__nv_bfloat16* ph, __nv_bfloat16* pl, float2 v) {
    __nv_bfloat16 hx = bf_hi(v.x), hy = bf_hi(v.y);
    __nv_bfloat162 h, l;
    h.x = hx; h.y = hy;
    l.x = bf_hi(v.x - __bfloat162float(hx)); l.y = bf_hi(v.y - __bfloat162float(hy));
    *(unsigned*)ph = *(unsigned*)&h;
    *(unsigned*)pl = *(unsigned*)&l;
}

// ---------------- prep: weight packing + row marking + cnt reset (one launch) ----
__global__ void prep(const float* __restrict__ Ws0, const float* __restrict__ Wn0,
                     const float* __restrict__ Ws1, const float* __restrict__ Wn1,
                     const float* __restrict__ Wp1, const float* __restrict__ Wp2,
                     const int* __restrict__ nidx1) {
    int b = blockIdx.x, t = threadIdx.x;
    if (b == 0 && t == 0) g_cnt = 0;
    if (b < HID) {
        int n = b, k = t;   // 256 x 256 transpose+split
        auto split1 = [](float v, __nv_bfloat16* h, __nv_bfloat16* l) {
            __nv_bfloat16 hb = __float2bfloat16_rn(v);
            *h = hb; *l = __float2bfloat16_rn(v - __bfloat162float(hb));
        };
        float w0 = (k < IN_DIM) ? Ws0[k * HID + n] : Wn0[(k - IN_DIM) * HID + n];
        split1(w0, &g_W0h[n * HID + k], &g_W0l[n * HID + k]);
        split1(Wp1[k * HID + n], &g_P1h[n * HID + k], &g_P1l[n * HID + k]);
        split1(Wp2[k * HID + n], &g_P2h[n * HID + k], &g_P2l[n * HID + k]);
        split1(Ws1[k * HID + n], &g_W1h[n * 2 * HID + k],       &g_W1l[n * 2 * HID + k]);
        split1(Wn1[k * HID + n], &g_W1h[n * 2 * HID + k + HID], &g_W1l[n * 2 * HID + k + HID]);
    } else {
        int e = (b - HID) * 256 + t;    // 480 blocks cover N2n*FAN = 122880
        g_flags[nidx1[e]] = 1;
    }
}

// ---------------- compaction (warp-aggregated atomics) ----------------
__global__ void compact_rows() {
    int i = blockIdx.x * blockDim.x + threadIdx.x;          // grid 480 x 256
    int lane = threadIdx.x & 31;
    int f = (i < N2n) || g_flags[i];                        // self rows always live
    unsigned m = __ballot_sync(0xffffffffu, f);
    int base = 0;
    if (lane == 0 && m) base = atomicAdd(&g_cnt, __popc(m));
    base = __shfl_sync(0xffffffffu, base, 0);
    if (f) {
        int p = base + __popc(m & ((1u << lane) - 1u));
        g_orig[p] = i;
        g_newid[i] = p;
    }
}

// ---------------- layer0 gather + mean -> bf16 hi/lo (compacted rows only) ----------------
__global__ void __launch_bounds__(256, 6) gather_agg0(
    const float* __restrict__ nf, const int* __restrict__ gids,
    const int* __restrict__ nidx) {
    int gw   = (blockIdx.x * blockDim.x + threadIdx.x) >> 5; // compacted row id
    int lane = threadIdx.x & 31;
    if (gw >= __ldg(&g_cnt)) return;
    int row = __ldg(&g_orig[gw]);                            // original dst row

    int idx_l = 0;
    if (lane < FAN)       idx_l = gids[nidx[(size_t)row * FAN + lane]];
    else if (lane == FAN) idx_l = gids[row];

    int gs = __shfl_sync(0xffffffffu, idx_l, FAN);
    float4 s = __ldg((const float4*)nf + (size_t)gs * (IN_DIM / 4) + lane);

    float4 aa = make_float4(0.f, 0.f, 0.f, 0.f), ab = aa;
    #pragma unroll
    for (int k = 0; k < FAN; k += 2) {
        int ga = __shfl_sync(0xffffffffu, idx_l, k);
        int gb = __shfl_sync(0xffffffffu, idx_l, k + 1);
        float4 va = __ldg((const float4*)nf + (size_t)ga * (IN_DIM / 4) + lane);
        float4 vb = __ldg((const float4*)nf + (size_t)gb * (IN_DIM / 4) + lane);
        aa.x += va.x; aa.y += va.y; aa.z += va.z; aa.w += va.w;
        ab.x += vb.x; ab.y += vb.y; ab.z += vb.z; ab.w += vb.w;
    }
    const float inv = 1.0f / FAN;
    float4 a = make_float4((aa.x + ab.x) * inv, (aa.y + ab.y) * inv,
                           (aa.z + ab.z) * inv, (aa.w + ab.w) * inv);

    size_t rb = (size_t)gw * HID;
    split_store4(g_u0h + rb + 4 * lane,       g_u0l + rb + 4 * lane,       s);
    split_store4(g_u0h + rb + 128 + 4 * lane, g_u0l + rb + 128 + 4 * lane, a);
}

// ---------------- layer1 gather + mean over compacted g_h0 -> bf16 hi/lo ----------------
__global__ void gather_agg1(const int* __restrict__ nidx) {
    int gw   = (blockIdx.x * blockDim.x + threadIdx.x) >> 5;
    int lane = threadIdx.x & 31;

    int idx_l = 0;
    if (lane < FAN)       idx_l = __ldg(&g_newid[nidx[(size_t)gw * FAN + lane]]);
    else if (lane == FAN) idx_l = __ldg(&g_newid[gw]);

    float4 a0 = make_float4(0.f, 0.f, 0.f, 0.f), a1 = a0;
    #pragma unroll
    for (int k = 0; k < FAN; k++) {
        int j = __shfl_sync(0xffffffffu, idx_l, k);
        const float4* row = (const float4*)g_h0 + (size_t)j * (HID / 4);
        float4 v0 = __ldg(row + lane);
        float4 v1 = __ldg(row + 32 + lane);
        a0.x += v0.x; a0.y += v0.y; a0.z += v0.z; a0.w += v0.w;
        a1.x += v1.x; a1.y += v1.y; a1.z += v1.z; a1.w += v1.w;
    }
    int js = __shfl_sync(0xffffffffu, idx_l, FAN);
    const float4* srow = (const float4*)g_h0 + (size_t)js * (HID / 4);
    float4 s0 = __ldg(srow + lane), s1 = __ldg(srow + 32 + lane);

    const float inv = 1.0f / FAN;
    a0.x *= inv; a0.y *= inv; a0.z *= inv; a0.w *= inv;
    a1.x *= inv; a1.y *= inv; a1.z *= inv; a1.w *= inv;

    size_t rb = (size_t)gw * (2 * HID);
    split_store4(g_u1h + rb + 4 * lane,       g_u1l + rb + 4 * lane,       s0);
    split_store4(g_u1h + rb + 128 + 4 * lane, g_u1l + rb + 128 + 4 * lane, s1);
    split_store4(g_u1h + rb + 256 + 4 * lane, g_u1l + rb + 256 + 4 * lane, a0);
    split_store4(g_u1h + rb + 384 + 4 * lane, g_u1l + rb + 384 + 4 * lane, a1);
}

// ---------------- HMMA GEMM: C[M,256] = act(A[M,K] @ W[K,256] + bias) ----------------
// A as bf16 hi/lo [M,K] row-major; W as transposed bf16 hi/lo Bt[256,K].
// 3-pass split: D += Ah*Bh + Ah*Bl + Al*Bh (fp32 accum via mma.sync.m16n8k16).
// Pass-outer MMA order: 16 independent mma between reuses of any accumulator
// (the pass-inner order created 3-deep HMMA RAW chains per tile).
// BM=128, BN=128, BK=32; 256 threads = 8 warps (2m x 4n), warp tile 64x32.
// smem: 2 stages x (Ah 8K | Al 8K | Bh 8K | Bl 8K) = 64 KB dynamic.
// Optional Mlim: device row-count; CTAs whose tile starts past it exit.
constexpr int GEMM_SMEM = 65536;

template <bool RELU, bool SPLIT>
__global__ void __launch_bounds__(256, 1) hgemm(
    const __nv_bfloat16* __restrict__ Ah, const __nv_bfloat16* __restrict__ Al,
    const __nv_bfloat16* __restrict__ Bh, const __nv_bfloat16* __restrict__ Bl,
    const float* __restrict__ bias,
    float* __restrict__ Cf, __nv_bfloat16* __restrict__ Ch, __nv_bfloat16* __restrict__ Cl,
    int K, const int* Mlim)
{
    extern __shared__ char sm[];
    const int bm = blockIdx.y * 128, bn = blockIdx.x * 128;
    if (Mlim != nullptr && bm >= __ldg(Mlim)) return;
    const uint32_t sb = smem_u32(sm);
    const int tid = threadIdx.x, lane = tid & 31, wid = tid >> 5;
    const int wm = (wid >> 2) * 64, wn = (wid & 3) * 32;
    const int nCh = K >> 5;                 // BK=32 chunks

    // smem tile offset: [128 rows][4 x 16B chunks], xor-swizzled chunk
    auto swo = [](int r, int c) -> uint32_t { return (uint32_t)(r * 64 + ((c ^ ((r >> 1) & 3)) << 4)); };

    auto load_stage = [&](int stage, int kc) {
        const uint32_t base = sb + stage * 32768;
        #pragma unroll
        for (int i = 0; i < 2; i++) {
            int q = tid + i * 256;          // 512 chunks per tile
            int r = q >> 2, c = q & 3;
            uint32_t so = swo(r, c);
            size_t ga = (size_t)(bm + r) * K + kc * 32 + c * 8;
            size_t gb = (size_t)(bn + r) * K + kc * 32 + c * 8;
            CP16(base +         so, Ah + ga);
            CP16(base +  8192 + so, Al + ga);
            CP16(base + 16384 + so, Bh + gb);
            CP16(base + 24576 + so, Bl + gb);
        }
    };

    float acc[4][4][4];
    #pragma unroll
    for (int i = 0; i < 4; i++)
        #pragma unroll
        for (int j = 0; j < 4; j++)
            #pragma unroll
            for (int k = 0; k < 4; k++) acc[i][j][k] = 0.f;

    load_stage(0, 0);
    CP_COMMIT();

    for (int kc = 0; kc < nCh; kc++) {
        if (kc + 1 < nCh) { load_stage((kc + 1) & 1, kc + 1); CP_COMMIT(); CP_WAIT1(); }
        else              { CP_WAIT0(); }
        __syncthreads();

        const uint32_t base = sb + (kc & 1) * 32768;
        #pragma unroll
        for (int ks = 0; ks < 2; ks++) {
            uint32_t aH[4][4], aL[4][4], bH[2][4], bL[2][4];
            #pragma unroll
            for (int mt = 0; mt < 4; mt++) {
                int row = wm + mt * 16 + (lane & 15);
                int kch = 2 * ks + (lane >> 4);
                uint32_t so = swo(row, kch);
                ldsm4(aH[mt], base + so);
                ldsm4(aL[mt], base + 8192 + so);
            }
            #pragma unroll
            for (int p = 0; p < 2; p++) {
                int row = wn + p * 16 + (lane & 7) + ((lane >> 4) << 3);
                int kch = 2 * ks + ((lane >> 3) & 1);
                uint32_t so = swo(row, kch);
                ldsm4(bH[p], base + 16384 + so);
                ldsm4(bL[p], base + 24576 + so);
            }
            // pass 1: Ah * Bh  (16 independent mma)
            #pragma unroll
            for (int mt = 0; mt < 4; mt++)
                #pragma unroll
                for (int nt = 0; nt < 4; nt++)
                    mma16816(acc[mt][nt], aH[mt], &bH[nt >> 1][(nt & 1) * 2]);
            // pass 2: Ah * Bl
            #pragma unroll
            for (int mt = 0; mt < 4; mt++)
                #pragma unroll
                for (int nt = 0; nt < 4; nt++)
                    mma16816(acc[mt][nt], aH[mt], &bL[nt >> 1][(nt & 1) * 2]);
            // pass 3: Al * Bh
            #pragma unroll
            for (int mt = 0; mt < 4; mt++)
                #pragma unroll
                for (int nt = 0; nt < 4; nt++)
                    mma16816(acc[mt][nt], aL[mt], &bH[nt >> 1][(nt & 1) * 2]);
        }
        __syncthreads();
    }

    // epilogue: direct float2 stores (+bias, act)
    const int tg = lane >> 2, tt = lane & 3;
    #pragma unroll
    for (int nt = 0; nt < 4; nt++) {
        int col = bn + wn + nt * 8 + 2 * tt;
        float2 b2 = *(const float2*)(bias + col);
        #pragma unroll
        for (int mt = 0; mt < 4; mt++) {
            int r0 = bm + wm + mt * 16 + tg;
            float2 v0, v1;
            v0.x = acc[mt][nt][0] + b2.x; v0.y = acc[mt][nt][1] + b2.y;
            v1.x = acc[mt][nt][2] + b2.x; v1.y = acc[mt][nt][3] + b2.y;
            if (RELU) {
                v0.x = fmaxf(v0.x, 0.f); v0.y = fmaxf(v0.y, 0.f);
                v1.x = fmaxf(v1.x, 0.f); v1.y = fmaxf(v1.y, 0.f);
            }
            size_t o0 = (size_t)r0 * 256 + col, o1 = o0 + 8 * 256;
            if (!SPLIT) {
                *(float2*)(Cf + o0) = v0;
                *(float2*)(Cf + o1) = v1;
            } else {
                split_store2(Ch + o0, Cl + o0, v0);
                split_store2(Ch + o1, Cl + o1, v1);
            }
        }
    }
}

// ---------------- z[r] = h2[r mod B] * h2[B + r], split to bf16 hi/lo ----------------
__global__ void build_z() {
    int r = blockIdx.x, c = threadIdx.x;   // grid 8192, block 64
    const float4* s = (const float4*)(g_h2 + (size_t)(r & (Bsz - 1)) * HID);
    const float4* o = (const float4*)(g_h2 + (size_t)(Bsz + r) * HID);
    float4 a = s[c], b = o[c];
    float4 v = make_float4(a.x * b.x, a.y * b.y, a.z * b.z, a.w * b.w);
    split_store4(g_zh + (size_t)r * HID + 4 * c, g_zl + (size_t)r * HID + 4 * c, v);
}

// ---------------- scores = z2 @ Wp3 + bp3 ----------------
__global__ void final_dot(const float* __restrict__ Wp3, const float* __restrict__ bp3,
                          float* __restrict__ out) {
    int gw   = (blockIdx.x * blockDim.x + threadIdx.x) >> 5;
    int lane = threadIdx.x & 31;
    const float4* z = (const float4*)(g_z2 + (size_t)gw * HID);
    const float4* w = (const float4*)Wp3;
    float4 z0 = z[lane], z1 = z[32 + lane];
    float4 w0 = __ldg(w + lane), w1 = __ldg(w + 32 + lane);
    float s = z0.x * w0.x + z0.y * w0.y + z0.z * w0.z + z0.w * w0.w
            + z1.x * w1.x + z1.y * w1.y + z1.z * w1.z + z1.w * w1.w;
    #pragma unroll
    for (int o = 16; o; o >>= 1) s += __shfl_xor_sync(0xffffffffu, s, o);
    if (lane == 0) out[gw] = s + bp3[0];
}

extern "C" void kernel_launch(void* const* d_in, const int* in_sizes, int n_in,
                              void* d_out, int out_size) {
    const float* node_feat = (const float*)d_in[0];
    const int*   gids0     = (const int*)d_in[1];
    const int*   nidx0     = (const int*)d_in[2];
    const int*   nidx1     = (const int*)d_in[3];
    const float* Ws0 = (const float*)d_in[4];
    const float* Wn0 = (const float*)d_in[5];
    const float* b0  = (const float*)d_in[6];
    const float* Ws1 = (const float*)d_in[7];
    const float* Wn1 = (const float*)d_in[8];
    const float* b1  = (const float*)d_in[9];
    const float* Wp1 = (const float*)d_in[10];
    const float* bp1 = (const float*)d_in[11];
    const float* Wp2 = (const float*)d_in[12];
    const float* bp2 = (const float*)d_in[13];
    const float* Wp3 = (const float*)d_in[14];
    const float* bp3 = (const float*)d_in[15];
    float* out = (float*)d_out;

    cudaFuncSetAttribute(hgemm<true,  false>, cudaFuncAttributeMaxDynamicSharedMemorySize, GEMM_SMEM);
    cudaFuncSetAttribute(hgemm<false, false>, cudaFuncAttributeMaxDynamicSharedMemorySize, GEMM_SMEM);
    cudaFuncSetAttribute(hgemm<true,  true >, cudaFuncAttributeMaxDynamicSharedMemorySize, GEMM_SMEM);

    __nv_bfloat16 *u0h, *u0l, *u1h, *u1l, *zh, *zl, *z1h, *z1l;
    __nv_bfloat16 *W0h, *W0l, *W1h, *W1l, *P1h, *P1l, *P2h, *P2l;
    float *h0, *h2, *z2;
    int* cnt;
    cudaGetSymbolAddress((void**)&u0h, g_u0h); cudaGetSymbolAddress((void**)&u0l, g_u0l);
    cudaGetSymbolAddress((void**)&u1h, g_u1h); cudaGetSymbolAddress((void**)&u1l, g_u1l);
    cudaGetSymbolAddress((void**)&zh,  g_zh);  cudaGetSymbolAddress((void**)&zl,  g_zl);
    cudaGetSymbolAddress((void**)&z1h, g_z1h); cudaGetSymbolAddress((void**)&z1l, g_z1l);
    cudaGetSymbolAddress((void**)&W0h, g_W0h); cudaGetSymbolAddress((void**)&W0l, g_W0l);
    cudaGetSymbolAddress((void**)&W1h, g_W1h); cudaGetSymbolAddress((void**)&W1l, g_W1l);
    cudaGetSymbolAddress((void**)&P1h, g_P1h); cudaGetSymbolAddress((void**)&P1l, g_P1l);
    cudaGetSymbolAddress((void**)&P2h, g_P2h); cudaGetSymbolAddress((void**)&P2l, g_P2l);
    cudaGetSymbolAddress((void**)&h0,  g_h0);  cudaGetSymbolAddress((void**)&h2,  g_h2);
    cudaGetSymbolAddress((void**)&z2,  g_z2);  cudaGetSymbolAddress((void**)&cnt, g_cnt);

    // (1) pack weights + mark live rows + reset counter
    prep<<<HID + (N2n * FAN) / 256, 256>>>(Ws0, Wn0, Ws1, Wn1, Wp1, Wp2, nidx1);
    // (2) compact live rows
    compact_rows<<<N1n / 256, 256>>>();
    // (3) layer 0 gather (compacted rows only)
    gather_agg0<<<N1n / 8, 256>>>(node_feat, gids0, nidx0);
    // (4) layer 0 GEMM — profiled launch
    hgemm<true, false><<<dim3(2, N1n / 128), 256, GEMM_SMEM>>>(
        u0h, u0l, W0h, W0l, b0, h0, nullptr, nullptr, 2 * IN_DIM, cnt);

    // layer 1
    gather_agg1<<<N2n / 8, 256>>>(nidx1);
    hgemm<false, false><<<dim3(2, N2n / 128), 256, GEMM_SMEM>>>(
        u1h, u1l, W1h, W1l, b1, h2, nullptr, nullptr, 2 * HID, nullptr);

    // edge MLP
    build_z<<<ZROWS, 64>>>();
    hgemm<true, true><<<dim3(2, ZROWS / 128), 256, GEMM_SMEM>>>(
        zh, zl, P1h, P1l, bp1, nullptr, z1h, z1l, HID, nullptr);
    hgemm<true, false><<<dim3(2, ZROWS / 128), 256, GEMM_SMEM>>>(
        z1h, z1l, P2h, P2l, bp2, z2, nullptr, nullptr, HID, nullptr);
    final_dot<<<ZROWS / 8, 256>>>(Wp3, bp3, out);
}

// round 10
// speedup vs baseline: 2.5750x; 1.0944x over previous
#include <cuda_runtime.h>
#include <cuda_bf16.h>
#include <cstdint>

#define FAN 10
constexpr int IN_DIM = 128;
constexpr int HID    = 256;
constexpr int Bsz    = 4096;
constexpr int N2n    = 3 * Bsz;       // 12288
constexpr int N1n    = N2n * FAN;     // 122880
constexpr int ZROWS  = 2 * Bsz;       // 8192

// ---------------- scratch (device globals: allocation-free) ----------------
__device__ __align__(16) __nv_bfloat16 g_u0h[(size_t)N1n * HID];
__device__ __align__(16) __nv_bfloat16 g_u0l[(size_t)N1n * HID];
__device__ __align__(16) float         g_h0 [(size_t)N1n * HID];
__device__ __align__(16) __nv_bfloat16 g_u1h[(size_t)N2n * 2 * HID];
__device__ __align__(16) __nv_bfloat16 g_u1l[(size_t)N2n * 2 * HID];
__device__ __align__(16) float         g_h2 [(size_t)N2n * HID];
__device__ __align__(16) __nv_bfloat16 g_zh [(size_t)ZROWS * HID];
__device__ __align__(16) __nv_bfloat16 g_zl [(size_t)ZROWS * HID];
__device__ __align__(16) __nv_bfloat16 g_z1h[(size_t)ZROWS * HID];
__device__ __align__(16) __nv_bfloat16 g_z1l[(size_t)ZROWS * HID];
__device__ __align__(16) float         g_z2 [(size_t)ZROWS * HID];
// transposed bf16 hi/lo weights: [N=256, K]
__device__ __align__(16) __nv_bfloat16 g_W0h[HID * HID],     g_W0l[HID * HID];
__device__ __align__(16) __nv_bfloat16 g_W1h[HID * 2 * HID], g_W1l[HID * 2 * HID];
__device__ __align__(16) __nv_bfloat16 g_P1h[HID * HID],     g_P1l[HID * HID];
__device__ __align__(16) __nv_bfloat16 g_P2h[HID * HID],     g_P2l[HID * HID];
// row compaction: only h0 rows referenced by layer 1 are computed.
// g_flags is zero-initialized at load; marks are idempotent writes of 1 with
// fixed inputs, so the marked set is identical on every call — no re-zeroing.
__device__ int g_cnt;                 // M' = number of live rows (reset in prep)
__device__ int g_flags[N1n];
__device__ int g_newid[N1n];          // original row -> compacted row
__device__ int g_orig [N1n];          // compacted row -> original row

// ---------------- PTX helpers (base sm_103-safe: mma.sync / ldmatrix / cp.async) ----
__device__ __forceinline__ uint32_t smem_u32(const void* p) {
    uint32_t a;
    asm("{ .reg .u64 t; cvta.to.shared.u64 t, %1; cvt.u32.u64 %0, t; }" : "=r"(a) : "l"(p));
    return a;
}
__device__ __forceinline__ void mma16816(float* d, const uint32_t* a, const uint32_t* b) {
    asm volatile("mma.sync.aligned.m16n8k16.row.col.f32.bf16.bf16.f32 "
                 "{%0,%1,%2,%3}, {%4,%5,%6,%7}, {%8,%9}, {%0,%1,%2,%3};"
                 : "+f"(d[0]), "+f"(d[1]), "+f"(d[2]), "+f"(d[3])
                 : "r"(a[0]), "r"(a[1]), "r"(a[2]), "r"(a[3]), "r"(b[0]), "r"(b[1]));
}
__device__ __forceinline__ void ldsm4(uint32_t* r, uint32_t addr) {
    asm volatile("ldmatrix.sync.aligned.m8n8.x4.shared.b16 {%0,%1,%2,%3}, [%4];"
                 : "=r"(r[0]), "=r"(r[1]), "=r"(r[2]), "=r"(r[3]) : "r"(addr));
}
#define CP16(dst, src) asm volatile("cp.async.cg.shared.global [%0], [%1], 16;" :: "r"(dst), "l"(src))
#define CP_COMMIT()    asm volatile("cp.async.commit_group;" ::: "memory")
#define CP_WAIT1()     asm volatile("cp.async.wait_group 1;" ::: "memory")
#define CP_WAIT0()     asm volatile("cp.async.wait_group 0;" ::: "memory")

// ---------------- bf16 hi/lo split helpers ----------------
__device__ __forceinline__ __nv_bfloat16 bf_hi(float v) { return __float2bfloat16_rn(v); }
__device__ __forceinline__ void split_store4(__nv_bfloat16* ph, __nv_bfloat16* pl, float4 v) {
    __nv_bfloat16 hx = bf_hi(v.x), hy = bf_hi(v.y), hz = bf_hi(v.z), hw = bf_hi(v.w);
    __nv_bfloat162 h01, h23, l01, l23;
    h01.x = hx; h01.y = hy; h23.x = hz; h23.y = hw;
    l01.x = bf_hi(v.x - __bfloat162float(hx)); l01.y = bf_hi(v.y - __bfloat162float(hy));
    l23.x = bf_hi(v.z - __bfloat162float(hz)); l23.y = bf_hi(v.w - __bfloat162float(hw));
    uint2 H, L;
    H.x = *(unsigned*)&h01; H.y = *(unsigned*)&h23;
    L.x = *(unsigned*)&l01; L.y = *(unsigned*)&l23;
    *(uint2*)ph = H; *(uint2*)pl = L;
}
__device__ __forceinline__ void split_store2(__nv_bfloat16* ph, __nv_bfloat16* pl, float2 v) {
    __nv_bfloat16 hx = bf_hi(v.x), hy = bf_hi(v.y);
    __nv_bfloat162 h, l;
    h.x = hx; h.y = hy;
    l.x = bf_hi(v.x - __bfloat162float(hx)); l.y = bf_hi(v.y - __bfloat162float(hy));
    *(unsigned*)ph = *(unsigned*)&h;
    *(unsigned*)pl = *(unsigned*)&l;
}

// ---------------- prep: weight packing + row marking + cnt reset (one launch) ----
__global__ void prep(const float* __restrict__ Ws0, const float* __restrict__ Wn0,
                     const float* __restrict__ Ws1, const float* __restrict__ Wn1,
                     const float* __restrict__ Wp1, const float* __restrict__ Wp2,
                     const int* __restrict__ nidx1) {
    int b = blockIdx.x, t = threadIdx.x;
    if (b == 0 && t == 0) g_cnt = 0;
    if (b < HID) {
        int n = b, k = t;   // 256 x 256 transpose+split
        auto split1 = [](float v, __nv_bfloat16* h, __nv_bfloat16* l) {
            __nv_bfloat16 hb = __float2bfloat16_rn(v);
            *h = hb; *l = __float2bfloat16_rn(v - __bfloat162float(hb));
        };
        float w0 = (k < IN_DIM) ? Ws0[k * HID + n] : Wn0[(k - IN_DIM) * HID + n];
        split1(w0, &g_W0h[n * HID + k], &g_W0l[n * HID + k]);
        split1(Wp1[k * HID + n], &g_P1h[n * HID + k], &g_P1l[n * HID + k]);
        split1(Wp2[k * HID + n], &g_P2h[n * HID + k], &g_P2l[n * HID + k]);
        split1(Ws1[k * HID + n], &g_W1h[n * 2 * HID + k],       &g_W1l[n * 2 * HID + k]);
        split1(Wn1[k * HID + n], &g_W1h[n * 2 * HID + k + HID], &g_W1l[n * 2 * HID + k + HID]);
    } else {
        int e = (b - HID) * 256 + t;    // 480 blocks cover N2n*FAN = 122880
        g_flags[nidx1[e]] = 1;
    }
}

// ---------------- compaction (warp-aggregated atomics) ----------------
__global__ void compact_rows() {
    int i = blockIdx.x * blockDim.x + threadIdx.x;          // grid 480 x 256
    int lane = threadIdx.x & 31;
    int f = (i < N2n) || g_flags[i];                        // self rows always live
    unsigned m = __ballot_sync(0xffffffffu, f);
    int base = 0;
    if (lane == 0 && m) base = atomicAdd(&g_cnt, __popc(m));
    base = __shfl_sync(0xffffffffu, base, 0);
    if (f) {
        int p = base + __popc(m & ((1u << lane) - 1u));
        g_orig[p] = i;
        g_newid[i] = p;
    }
}

// ---------------- layer0 gather + mean -> bf16 hi/lo (compacted rows only) ----------------
__global__ void __launch_bounds__(256, 6) gather_agg0(
    const float* __restrict__ nf, const int* __restrict__ gids,
    const int* __restrict__ nidx) {
    int gw   = (blockIdx.x * blockDim.x + threadIdx.x) >> 5; // compacted row id
    int lane = threadIdx.x & 31;
    if (gw >= __ldg(&g_cnt)) return;
    int row = __ldg(&g_orig[gw]);                            // original dst row

    int idx_l = 0;
    if (lane < FAN)       idx_l = gids[nidx[(size_t)row * FAN + lane]];
    else if (lane == FAN) idx_l = gids[row];

    int gs = __shfl_sync(0xffffffffu, idx_l, FAN);
    float4 s = __ldg((const float4*)nf + (size_t)gs * (IN_DIM / 4) + lane);

    float4 aa = make_float4(0.f, 0.f, 0.f, 0.f), ab = aa;
    #pragma unroll
    for (int k = 0; k < FAN; k += 2) {
        int ga = __shfl_sync(0xffffffffu, idx_l, k);
        int gb = __shfl_sync(0xffffffffu, idx_l, k + 1);
        float4 va = __ldg((const float4*)nf + (size_t)ga * (IN_DIM / 4) + lane);
        float4 vb = __ldg((const float4*)nf + (size_t)gb * (IN_DIM / 4) + lane);
        aa.x += va.x; aa.y += va.y; aa.z += va.z; aa.w += va.w;
        ab.x += vb.x; ab.y += vb.y; ab.z += vb.z; ab.w += vb.w;
    }
    const float inv = 1.0f / FAN;
    float4 a = make_float4((aa.x + ab.x) * inv, (aa.y + ab.y) * inv,
                           (aa.z + ab.z) * inv, (aa.w + ab.w) * inv);

    size_t rb = (size_t)gw * HID;
    split_store4(g_u0h + rb + 4 * lane,       g_u0l + rb + 4 * lane,       s);
    split_store4(g_u0h + rb + 128 + 4 * lane, g_u0l + rb + 128 + 4 * lane, a);
}

// ---------------- layer1 gather + mean over compacted g_h0 -> bf16 hi/lo ----------------
__global__ void gather_agg1(const int* __restrict__ nidx) {
    int gw   = (blockIdx.x * blockDim.x + threadIdx.x) >> 5;
    int lane = threadIdx.x & 31;

    int idx_l = 0;
    if (lane < FAN)       idx_l = __ldg(&g_newid[nidx[(size_t)gw * FAN + lane]]);
    else if (lane == FAN) idx_l = __ldg(&g_newid[gw]);

    float4 a0 = make_float4(0.f, 0.f, 0.f, 0.f), a1 = a0;
    #pragma unroll
    for (int k = 0; k < FAN; k++) {
        int j = __shfl_sync(0xffffffffu, idx_l, k);
        const float4* row = (const float4*)g_h0 + (size_t)j * (HID / 4);
        float4 v0 = __ldg(row + lane);
        float4 v1 = __ldg(row + 32 + lane);
        a0.x += v0.x; a0.y += v0.y; a0.z += v0.z; a0.w += v0.w;
        a1.x += v1.x; a1.y += v1.y; a1.z += v1.z; a1.w += v1.w;
    }
    int js = __shfl_sync(0xffffffffu, idx_l, FAN);
    const float4* srow = (const float4*)g_h0 + (size_t)js * (HID / 4);
    float4 s0 = __ldg(srow + lane), s1 = __ldg(srow + 32 + lane);

    const float inv = 1.0f / FAN;
    a0.x *= inv; a0.y *= inv; a0.z *= inv; a0.w *= inv;
    a1.x *= inv; a1.y *= inv; a1.z *= inv; a1.w *= inv;

    size_t rb = (size_t)gw * (2 * HID);
    split_store4(g_u1h + rb + 4 * lane,       g_u1l + rb + 4 * lane,       s0);
    split_store4(g_u1h + rb + 128 + 4 * lane, g_u1l + rb + 128 + 4 * lane, s1);
    split_store4(g_u1h + rb + 256 + 4 * lane, g_u1l + rb + 256 + 4 * lane, a0);
    split_store4(g_u1h + rb + 384 + 4 * lane, g_u1l + rb + 384 + 4 * lane, a1);
}

// ---------------- HMMA GEMM: C[M,256] = act(A[M,K] @ W[K,256] + bias) ----------------
// A as bf16 hi/lo [M,K] row-major; W as transposed bf16 hi/lo Bt[256,K].
// 3-pass split: D += Ah*Bh + Ah*Bl + Al*Bh (fp32 accum via mma.sync.m16n8k16).
// Occupancy 2 CTAs/SM (the R9 profile showed tensor=50% @ occ=12.4%, 1 CTA/SM:
// ldsm/sync phases left the tensor pipe idle). To fit 2 CTAs at <=128 regs the
// A-fragment registers are REUSED: load Ah -> pass1(Ah*Bh), pass2(Ah*Bl), then
// reload the same regs with Al -> pass3(Al*Bh). Max live ~96 regs.
// BM=128, BN=128, BK=32; 256 threads = 8 warps (2m x 4n), warp tile 64x32.
// smem: 2 stages x 32KB = 64KB dynamic (2 CTAs x 64KB = 128KB <= 228KB/SM).
constexpr int GEMM_SMEM = 65536;

template <bool RELU, bool SPLIT>
__global__ void __launch_bounds__(256, 2) hgemm(
    const __nv_bfloat16* __restrict__ Ah, const __nv_bfloat16* __restrict__ Al,
    const __nv_bfloat16* __restrict__ Bh, const __nv_bfloat16* __restrict__ Bl,
    const float* __restrict__ bias,
    float* __restrict__ Cf, __nv_bfloat16* __restrict__ Ch, __nv_bfloat16* __restrict__ Cl,
    int K, const int* Mlim)
{
    extern __shared__ char sm[];
    const int bm = blockIdx.y * 128, bn = blockIdx.x * 128;
    if (Mlim != nullptr && bm >= __ldg(Mlim)) return;
    const uint32_t sb = smem_u32(sm);
    const int tid = threadIdx.x, lane = tid & 31, wid = tid >> 5;
    const int wm = (wid >> 2) * 64, wn = (wid & 3) * 32;
    const int nCh = K >> 5;                 // BK=32 chunks

    // smem tile offset: [128 rows][4 x 16B chunks], xor-swizzled chunk
    auto swo = [](int r, int c) -> uint32_t { return (uint32_t)(r * 64 + ((c ^ ((r >> 1) & 3)) << 4)); };

    auto load_stage = [&](int stage, int kc) {
        const uint32_t base = sb + stage * 32768;
        #pragma unroll
        for (int i = 0; i < 2; i++) {
            int q = tid + i * 256;          // 512 chunks per tile
            int r = q >> 2, c = q & 3;
            uint32_t so = swo(r, c);
            size_t ga = (size_t)(bm + r) * K + kc * 32 + c * 8;
            size_t gb = (size_t)(bn + r) * K + kc * 32 + c * 8;
            CP16(base +         so, Ah + ga);
            CP16(base +  8192 + so, Al + ga);
            CP16(base + 16384 + so, Bh + gb);
            CP16(base + 24576 + so, Bl + gb);
        }
    };

    float acc[4][4][4];
    #pragma unroll
    for (int i = 0; i < 4; i++)
        #pragma unroll
        for (int j = 0; j < 4; j++)
            #pragma unroll
            for (int k = 0; k < 4; k++) acc[i][j][k] = 0.f;

    load_stage(0, 0);
    CP_COMMIT();

    for (int kc = 0; kc < nCh; kc++) {
        if (kc + 1 < nCh) { load_stage((kc + 1) & 1, kc + 1); CP_COMMIT(); CP_WAIT1(); }
        else              { CP_WAIT0(); }
        __syncthreads();

        const uint32_t base = sb + (kc & 1) * 32768;
        #pragma unroll
        for (int ks = 0; ks < 2; ks++) {
            uint32_t aR[4][4], bH[2][4], bL[2][4];
            const int akch = 2 * ks + (lane >> 4);
            const int arow = wm + (lane & 15);
            #pragma unroll
            for (int p = 0; p < 2; p++) {
                int row = wn + p * 16 + (lane & 7) + ((lane >> 4) << 3);
                int kch = 2 * ks + ((lane >> 3) & 1);
                uint32_t so = swo(row, kch);
                ldsm4(bH[p], base + 16384 + so);
                ldsm4(bL[p], base + 24576 + so);
            }
            #pragma unroll
            for (int mt = 0; mt < 4; mt++)
                ldsm4(aR[mt], base + swo(arow + mt * 16, akch));
            // pass 1: Ah * Bh  (16 independent mma)
            #pragma unroll
            for (int mt = 0; mt < 4; mt++)
                #pragma unroll
                for (int nt = 0; nt < 4; nt++)
                    mma16816(acc[mt][nt], aR[mt], &bH[nt >> 1][(nt & 1) * 2]);
            // pass 2: Ah * Bl
            #pragma unroll
            for (int mt = 0; mt < 4; mt++)
                #pragma unroll
                for (int nt = 0; nt < 4; nt++)
                    mma16816(acc[mt][nt], aR[mt], &bL[nt >> 1][(nt & 1) * 2]);
            // reload A fragments with Al (reuses aR registers; Ah now dead)
            #pragma unroll
            for (int mt = 0; mt < 4; mt++)
                ldsm4(aR[mt], base + 8192 + swo(arow + mt * 16, akch));
            // pass 3: Al * Bh
            #pragma unroll
            for (int mt = 0; mt < 4; mt++)
                #pragma unroll
                for (int nt = 0; nt < 4; nt++)
                    mma16816(acc[mt][nt], aR[mt], &bH[nt >> 1][(nt & 1) * 2]);
        }
        __syncthreads();
    }

    // epilogue: direct float2 stores (+bias, act)
    const int tg = lane >> 2, tt = lane & 3;
    #pragma unroll
    for (int nt = 0; nt < 4; nt++) {
        int col = bn + wn + nt * 8 + 2 * tt;
        float2 b2 = *(const float2*)(bias + col);
        #pragma unroll
        for (int mt = 0; mt < 4; mt++) {
            int r0 = bm + wm + mt * 16 + tg;
            float2 v0, v1;
            v0.x = acc[mt][nt][0] + b2.x; v0.y = acc[mt][nt][1] + b2.y;
            v1.x = acc[mt][nt][2] + b2.x; v1.y = acc[mt][nt][3] + b2.y;
            if (RELU) {
                v0.x = fmaxf(v0.x, 0.f); v0.y = fmaxf(v0.y, 0.f);
                v1.x = fmaxf(v1.x, 0.f); v1.y = fmaxf(v1.y, 0.f);
            }
            size_t o0 = (size_t)r0 * 256 + col, o1 = o0 + 8 * 256;
            if (!SPLIT) {
                *(float2*)(Cf + o0) = v0;
                *(float2*)(Cf + o1) = v1;
            } else {
                split_store2(Ch + o0, Cl + o0, v0);
                split_store2(Ch + o1, Cl + o1, v1);
            }
        }
    }
}

// ---------------- z[r] = h2[r mod B] * h2[B + r], split to bf16 hi/lo ----------------
__global__ void build_z() {
    int r = blockIdx.x, c = threadIdx.x;   // grid 8192, block 64
    const float4* s = (const float4*)(g_h2 + (size_t)(r & (Bsz - 1)) * HID);
    const float4* o = (const float4*)(g_h2 + (size_t)(Bsz + r) * HID);
    float4 a = s[c], b = o[c];
    float4 v = make_float4(a.x * b.x, a.y * b.y, a.z * b.z, a.w * b.w);
    split_store4(g_zh + (size_t)r * HID + 4 * c, g_zl + (size_t)r * HID + 4 * c, v);
}

// ---------------- scores = z2 @ Wp3 + bp3 ----------------
__global__ void final_dot(const float* __restrict__ Wp3, const float* __restrict__ bp3,
                          float* __restrict__ out) {
    int gw   = (blockIdx.x * blockDim.x + threadIdx.x) >> 5;
    int lane = threadIdx.x & 31;
    const float4* z = (const float4*)(g_z2 + (size_t)gw * HID);
    const float4* w = (const float4*)Wp3;
    float4 z0 = z[lane], z1 = z[32 + lane];
    float4 w0 = __ldg(w + lane), w1 = __ldg(w + 32 + lane);
    float s = z0.x * w0.x + z0.y * w0.y + z0.z * w0.z + z0.w * w0.w
            + z1.x * w1.x + z1.y * w1.y + z1.z * w1.z + z1.w * w1.w;
    #pragma unroll
    for (int o = 16; o; o >>= 1) s += __shfl_xor_sync(0xffffffffu, s, o);
    if (lane == 0) out[gw] = s + bp3[0];
}

extern "C" void kernel_launch(void* const* d_in, const int* in_sizes, int n_in,
                              void* d_out, int out_size) {
    const float* node_feat = (const float*)d_in[0];
    const int*   gids0     = (const int*)d_in[1];
    const int*   nidx0     = (const int*)d_in[2];
    const int*   nidx1     = (const int*)d_in[3];
    const float* Ws0 = (const float*)d_in[4];
    const float* Wn0 = (const float*)d_in[5];
    const float* b0  = (const float*)d_in[6];
    const float* Ws1 = (const float*)d_in[7];
    const float* Wn1 = (const float*)d_in[8];
    const float* b1  = (const float*)d_in[9];
    const float* Wp1 = (const float*)d_in[10];
    const float* bp1 = (const float*)d_in[11];
    const float* Wp2 = (const float*)d_in[12];
    const float* bp2 = (const float*)d_in[13];
    const float* Wp3 = (const float*)d_in[14];
    const float* bp3 = (const float*)d_in[15];
    float* out = (float*)d_out;

    cudaFuncSetAttribute(hgemm<true,  false>, cudaFuncAttributeMaxDynamicSharedMemorySize, GEMM_SMEM);
    cudaFuncSetAttribute(hgemm<false, false>, cudaFuncAttributeMaxDynamicSharedMemorySize, GEMM_SMEM);
    cudaFuncSetAttribute(hgemm<true,  true >, cudaFuncAttributeMaxDynamicSharedMemorySize, GEMM_SMEM);

    __nv_bfloat16 *u0h, *u0l, *u1h, *u1l, *zh, *zl, *z1h, *z1l;
    __nv_bfloat16 *W0h, *W0l, *W1h, *W1l, *P1h, *P1l, *P2h, *P2l;
    float *h0, *h2, *z2;
    int* cnt;
    cudaGetSymbolAddress((void**)&u0h, g_u0h); cudaGetSymbolAddress((void**)&u0l, g_u0l);
    cudaGetSymbolAddress((void**)&u1h, g_u1h); cudaGetSymbolAddress((void**)&u1l, g_u1l);
    cudaGetSymbolAddress((void**)&zh,  g_zh);  cudaGetSymbolAddress((void**)&zl,  g_zl);
    cudaGetSymbolAddress((void**)&z1h, g_z1h); cudaGetSymbolAddress((void**)&z1l, g_z1l);
    cudaGetSymbolAddress((void**)&W0h, g_W0h); cudaGetSymbolAddress((void**)&W0l, g_W0l);
    cudaGetSymbolAddress((void**)&W1h, g_W1h); cudaGetSymbolAddress((void**)&W1l, g_W1l);
    cudaGetSymbolAddress((void**)&P1h, g_P1h); cudaGetSymbolAddress((void**)&P1l, g_P1l);
    cudaGetSymbolAddress((void**)&P2h, g_P2h); cudaGetSymbolAddress((void**)&P2l, g_P2l);
    cudaGetSymbolAddress((void**)&h0,  g_h0);  cudaGetSymbolAddress((void**)&h2,  g_h2);
    cudaGetSymbolAddress((void**)&z2,  g_z2);  cudaGetSymbolAddress((void**)&cnt, g_cnt);

    // (1) pack weights + mark live rows + reset counter
    prep<<<HID + (N2n * FAN) / 256, 256>>>(Ws0, Wn0, Ws1, Wn1, Wp1, Wp2, nidx1);
    // (2) compact live rows
    compact_rows<<<N1n / 256, 256>>>();
    // (3) layer 0 gather (compacted rows only)
    gather_agg0<<<N1n / 8, 256>>>(node_feat, gids0, nidx0);
    // (4) layer 0 GEMM — profiled launch
    hgemm<true, false><<<dim3(2, N1n / 128), 256, GEMM_SMEM>>>(
        u0h, u0l, W0h, W0l, b0, h0, nullptr, nullptr, 2 * IN_DIM, cnt);

    // layer 1
    gather_agg1<<<N2n / 8, 256>>>(nidx1);
    hgemm<false, false><<<dim3(2, N2n / 128), 256, GEMM_SMEM>>>(
        u1h, u1l, W1h, W1l, b1, h2, nullptr, nullptr, 2 * HID, nullptr);

    // edge MLP
    build_z<<<ZROWS, 64>>>();
    hgemm<true, true><<<dim3(2, ZROWS / 128), 256, GEMM_SMEM>>>(
        zh, zl, P1h, P1l, bp1, nullptr, z1h, z1l, HID, nullptr);
    hgemm<true, false><<<dim3(2, ZROWS / 128), 256, GEMM_SMEM>>>(
        z1h, z1l, P2h, P2l, bp2, z2, nullptr, nullptr, HID, nullptr);
    final_dot<<<ZROWS / 8, 256>>>(Wp3, bp3, out);
}